// round 6
// baseline (speedup 1.0000x reference)
#include <cuda_runtime.h>

// Problem constants
#define BB  16
#define CC  256
#define HW  4096
#define EE  4
#define HID 128
#define RHD 128
#define ICB 8          // conv input-channel chunk

// ---------------- device-global scratch (allowed; no dynamic alloc) ----------
__device__ __align__(16) float g_pooled[BB * CC];
__device__ int   g_expert[BB];
__device__ float g_weight[BB];
__device__ __align__(16) float g_y1[(size_t)BB * HID * HW];   // 32 MB
__device__ __align__(16) float g_y2[(size_t)BB * HID * HW];   // 32 MB

typedef unsigned long long u64;

// ---------------- packed f32x2 helpers (sm_100+ FFMA2) -----------------------
__device__ __forceinline__ u64 pack2(float lo, float hi) {
    u64 r; asm("mov.b64 %0, {%1, %2};" : "=l"(r) : "f"(lo), "f"(hi)); return r;
}
__device__ __forceinline__ void unpack2(u64 v, float& lo, float& hi) {
    asm("mov.b64 {%0, %1}, %2;" : "=f"(lo), "=f"(hi) : "l"(v));
}
__device__ __forceinline__ void fma2(u64& acc, u64 a, u64 b) {
    asm("fma.rn.f32x2 %0, %1, %2, %0;" : "+l"(acc) : "l"(a), "l"(b));
}

// ============================================================================
// Kernel 1: global average pool.  grid = B*C blocks, 256 threads.
// ============================================================================
__global__ void pool_kernel(const float* __restrict__ x) {
    int bc = blockIdx.x;
    const float4* p = (const float4*)(x + (size_t)bc * HW);
    float s = 0.f;
    #pragma unroll
    for (int i = threadIdx.x; i < HW / 4; i += 256) {
        float4 v = p[i];
        s += (v.x + v.y) + (v.z + v.w);
    }
    __shared__ float red[8];
    #pragma unroll
    for (int o = 16; o > 0; o >>= 1) s += __shfl_down_sync(0xffffffffu, s, o);
    if ((threadIdx.x & 31) == 0) red[threadIdx.x >> 5] = s;
    __syncthreads();
    if (threadIdx.x < 8) {
        s = red[threadIdx.x];
        #pragma unroll
        for (int o = 4; o > 0; o >>= 1) s += __shfl_down_sync(0xffu, s, o);
        if (threadIdx.x == 0) g_pooled[bc] = s * (1.0f / (float)HW);
    }
}

// ============================================================================
// Kernel 2: router MLP + softmax + top-1.  grid = B, 128 threads.
// ============================================================================
__global__ void router_kernel(const float* __restrict__ Wr1, const float* __restrict__ br1,
                              const float* __restrict__ Wr2, const float* __restrict__ br2) {
    int b = blockIdx.x;
    int t = threadIdx.x;
    __shared__ float sp[CC];
    __shared__ float sh[RHD];
    __shared__ float slog[EE];
    sp[t]       = g_pooled[b * CC + t];
    sp[t + 128] = g_pooled[b * CC + t + 128];
    __syncthreads();
    {
        float acc = br1[t];
        const float* w = Wr1 + (size_t)t * CC;
        #pragma unroll 8
        for (int c = 0; c < CC; c++) acc = fmaf(sp[c], w[c], acc);
        sh[t] = fmaxf(acc, 0.f);
    }
    __syncthreads();
    if (t < EE) {
        float l = br2[t];
        const float* w = Wr2 + (size_t)t * RHD;
        #pragma unroll 8
        for (int r = 0; r < RHD; r++) l = fmaf(sh[r], w[r], l);
        slog[t] = l;
    }
    __syncthreads();
    if (t == 0) {
        float l0 = slog[0], l1 = slog[1], l2 = slog[2], l3 = slog[3];
        float m = fmaxf(fmaxf(l0, l1), fmaxf(l2, l3));
        float e0 = __expf(l0 - m), e1 = __expf(l1 - m), e2 = __expf(l2 - m), e3 = __expf(l3 - m);
        float s = e0 + e1 + e2 + e3;
        float p[4] = {e0 / s, e1 / s, e2 / s, e3 / s};
        int idx = 0; float v = p[0];
        #pragma unroll
        for (int i = 1; i < 4; i++) { if (p[i] > v) { v = p[i]; idx = i; } }
        g_expert[b] = idx;
        g_weight[b] = v / (v + 1e-9f);
    }
}

// ============================================================================
// Kernel 3: 1x1 conv C->HID with ReLU (GEMM M=128, N=4096, K=256 per batch).
// A tile stored PRE-DUPLICATED as u64 -> inner loop has zero packs.
// ============================================================================
__global__ __launch_bounds__(256, 2) void gemm1_kernel(const float* __restrict__ x,
                                                       const float* __restrict__ W1) {
    __shared__ __align__(16) u64   As2[16][128];  // [k][m], value duplicated in both lanes
    __shared__ __align__(16) float Bs[16][128];   // [k][n]
    int b  = blockIdx.y;
    int pt = blockIdx.x * 128;
    int e  = g_expert[b];
    const float* W = W1 + (size_t)e * (HID * CC);       // [128][256]
    const float* X = x  + (size_t)b * CC * HW;          // [256][4096]

    u64 acc[8][4];
    #pragma unroll
    for (int i = 0; i < 8; i++)
        #pragma unroll
        for (int j = 0; j < 4; j++) acc[i][j] = 0ULL;

    int tid = threadIdx.x;
    int ty = tid >> 4, tx = tid & 15;
    int am = tid >> 1, ak = (tid & 1) << 3;
    int bk = tid >> 4, bn = (tid & 15) << 3;

    for (int kb = 0; kb < CC; kb += 16) {
        float a[8];
        *(float4*)&a[0] = *(const float4*)(W + (size_t)am * CC + kb + ak);
        *(float4*)&a[4] = *(const float4*)(W + (size_t)am * CC + kb + ak + 4);
        float4 b0 = *(const float4*)(X + (size_t)(kb + bk) * HW + pt + bn);
        float4 b1 = *(const float4*)(X + (size_t)(kb + bk) * HW + pt + bn + 4);
        #pragma unroll
        for (int t = 0; t < 8; t++) As2[ak + t][am] = pack2(a[t], a[t]);
        *(float4*)&Bs[bk][bn]     = b0;
        *(float4*)&Bs[bk][bn + 4] = b1;
        __syncthreads();
        #pragma unroll
        for (int k = 0; k < 16; k++) {
            u64 av[8];
            #pragma unroll
            for (int i = 0; i < 8; i++) av[i] = As2[k][ty * 8 + i];   // LDS.64 broadcast
            u64 bv[4];
            #pragma unroll
            for (int j = 0; j < 4; j++) bv[j] = *(const u64*)&Bs[k][tx * 8 + 2 * j];
            #pragma unroll
            for (int i = 0; i < 8; i++)
                #pragma unroll
                for (int j = 0; j < 4; j++) fma2(acc[i][j], av[i], bv[j]);
        }
        __syncthreads();
    }
    float* Y = g_y1 + (size_t)b * HID * HW + pt;
    #pragma unroll
    for (int i = 0; i < 8; i++) {
        float o8[8];
        #pragma unroll
        for (int j = 0; j < 4; j++) {
            float lo, hi; unpack2(acc[i][j], lo, hi);
            o8[2 * j]     = fmaxf(lo, 0.f);
            o8[2 * j + 1] = fmaxf(hi, 0.f);
        }
        float4* dst = (float4*)(Y + (size_t)(ty * 8 + i) * HW + tx * 8);
        dst[0] = *(float4*)&o8[0];
        dst[1] = *(float4*)&o8[4];
    }
}

// ============================================================================
// Kernel 4: 3x3 conv HID->HID with ReLU.
// Weights pre-duplicated as u64 in smem (broadcast LDS.64, no packs).
// Even input pairs loaded directly as aligned LDS.64; only odd pairs packed.
// Block: 32 oc x 16x16 px tile; thread: 4 oc x 8 px. IC chunk = 8.
// ============================================================================
__global__ __launch_bounds__(256, 2) void conv3_kernel(const float* __restrict__ W2) {
    __shared__ __align__(16) float sin_[ICB][18][18];   // 10.4 KB, [ic][y][x] + halo
    __shared__ __align__(16) u64   sw2[32][ICB][9];     // 18.4 KB, duplicated weights
    int b   = blockIdx.z;
    int ocb = blockIdx.y * 32;
    int ty0 = (blockIdx.x >> 2) << 4;
    int tx0 = (blockIdx.x & 3) << 4;
    int e   = g_expert[b];
    const float* W  = W2   + (size_t)e * HID * HID * 9;  // [oc][ic][9]
    const float* Y1 = g_y1 + (size_t)b * HID * HW;

    int tid = threadIdx.x;
    int ocg = tid >> 5;            // warp-uniform oc group (broadcast weight loads)
    int pxg = tid & 31;
    int r   = pxg >> 1;            // row in tile 0..15
    int ch  = (pxg & 1) << 3;      // col base 0 or 8 (even -> 8B aligned in sin_)

    u64 acc[4][4];
    #pragma unroll
    for (int o = 0; o < 4; o++)
        #pragma unroll
        for (int j = 0; j < 4; j++) acc[o][j] = 0ULL;

    for (int kcb = 0; kcb < HID; kcb += ICB) {
        __syncthreads();
        // input tile with halo (zero padding at image borders): 8*18*18 = 2592
        for (int idx = tid; idx < ICB * 18 * 18; idx += 256) {
            int c  = idx / 324; int rem = idx - c * 324;
            int iy = rem / 18;  int ix  = rem - iy * 18;
            int gy = ty0 + iy - 1, gx = tx0 + ix - 1;
            float v = 0.f;
            if ((unsigned)gy < 64u && (unsigned)gx < 64u)
                v = Y1[(size_t)(kcb + c) * HW + gy * 64 + gx];
            sin_[c][iy][ix] = v;
        }
        // weights, packed once here instead of 36x per kc per thread: 32*8*9 = 2304
        for (int idx = tid; idx < 32 * ICB * 9; idx += 256) {
            int oc = idx / (ICB * 9); int rem = idx - oc * (ICB * 9);
            int ic = rem / 9;         int tap = rem - ic * 9;
            float w = W[((size_t)(ocb + oc) * HID + (kcb + ic)) * 9 + tap];
            sw2[oc][ic][tap] = pack2(w, w);
        }
        __syncthreads();
        #pragma unroll
        for (int kc = 0; kc < ICB; kc++) {
            #pragma unroll
            for (int ky = 0; ky < 3; ky++) {
                // even pairs: direct aligned LDS.64 (cols ch..ch+9)
                u64 ev[5];
                #pragma unroll
                for (int t = 0; t < 5; t++)
                    ev[t] = *(const u64*)&sin_[kc][r + ky][ch + 2 * t];
                // odd pairs: [2t+1, 2t+2] from halves of ev (extractions are free)
                float f[10];
                #pragma unroll
                for (int t = 0; t < 5; t++) unpack2(ev[t], f[2 * t], f[2 * t + 1]);
                u64 od[4];
                #pragma unroll
                for (int t = 0; t < 4; t++) od[t] = pack2(f[2 * t + 1], f[2 * t + 2]);
                #pragma unroll
                for (int kx = 0; kx < 3; kx++) {
                    const u64* ip = (kx == 0) ? &ev[0] : (kx == 1) ? &od[0] : &ev[1];
                    #pragma unroll
                    for (int o = 0; o < 4; o++) {
                        u64 wp = sw2[ocg * 4 + o][kc][ky * 3 + kx];   // broadcast LDS.64
                        #pragma unroll
                        for (int j = 0; j < 4; j++) fma2(acc[o][j], wp, ip[j]);
                    }
                }
            }
        }
    }
    float* Y2 = g_y2 + (size_t)b * HID * HW;
    int pix = (ty0 + r) * 64 + tx0 + ch;
    #pragma unroll
    for (int o = 0; o < 4; o++) {
        float o8[8];
        #pragma unroll
        for (int j = 0; j < 4; j++) {
            float lo, hi; unpack2(acc[o][j], lo, hi);
            o8[2 * j]     = fmaxf(lo, 0.f);
            o8[2 * j + 1] = fmaxf(hi, 0.f);
        }
        float4* d = (float4*)(Y2 + (size_t)(ocb + ocg * 4 + o) * HW + pix);
        d[0] = *(float4*)&o8[0];
        d[1] = *(float4*)&o8[4];
    }
}

// ============================================================================
// Kernel 5: 1x1 conv HID->C, scaled by routing weight, + residual.
// Same duplicated-A optimization. GEMM M=256, N=4096, K=128.
// ============================================================================
__global__ __launch_bounds__(256, 2) void gemm3_kernel(const float* __restrict__ x,
                                                       const float* __restrict__ W3,
                                                       float* __restrict__ out) {
    __shared__ __align__(16) u64   As2[16][128];
    __shared__ __align__(16) float Bs[16][128];
    int b  = blockIdx.z;
    int m0 = blockIdx.y * 128;
    int pt = blockIdx.x * 128;
    int e  = g_expert[b];
    float wgt = g_weight[b];
    const float* W  = W3   + (size_t)e * (CC * HID) + (size_t)m0 * HID;
    const float* Y2 = g_y2 + (size_t)b * HID * HW;

    u64 acc[8][4];
    #pragma unroll
    for (int i = 0; i < 8; i++)
        #pragma unroll
        for (int j = 0; j < 4; j++) acc[i][j] = 0ULL;

    int tid = threadIdx.x;
    int ty = tid >> 4, tx = tid & 15;
    int am = tid >> 1, ak = (tid & 1) << 3;
    int bk = tid >> 4, bn = (tid & 15) << 3;

    for (int kb = 0; kb < HID; kb += 16) {
        float a[8];
        *(float4*)&a[0] = *(const float4*)(W + (size_t)am * HID + kb + ak);
        *(float4*)&a[4] = *(const float4*)(W + (size_t)am * HID + kb + ak + 4);
        float4 b0 = *(const float4*)(Y2 + (size_t)(kb + bk) * HW + pt + bn);
        float4 b1 = *(const float4*)(Y2 + (size_t)(kb + bk) * HW + pt + bn + 4);
        #pragma unroll
        for (int t = 0; t < 8; t++) As2[ak + t][am] = pack2(a[t], a[t]);
        *(float4*)&Bs[bk][bn]     = b0;
        *(float4*)&Bs[bk][bn + 4] = b1;
        __syncthreads();
        #pragma unroll
        for (int k = 0; k < 16; k++) {
            u64 av[8];
            #pragma unroll
            for (int i = 0; i < 8; i++) av[i] = As2[k][ty * 8 + i];
            u64 bv[4];
            #pragma unroll
            for (int j = 0; j < 4; j++) bv[j] = *(const u64*)&Bs[k][tx * 8 + 2 * j];
            #pragma unroll
            for (int i = 0; i < 8; i++)
                #pragma unroll
                for (int j = 0; j < 4; j++) fma2(acc[i][j], av[i], bv[j]);
        }
        __syncthreads();
    }
    const float* Xr = x   + (size_t)b * CC * HW + pt;
    float*       O  = out + (size_t)b * CC * HW + pt;
    #pragma unroll
    for (int i = 0; i < 8; i++) {
        int m = m0 + ty * 8 + i;
        float o8[8];
        #pragma unroll
        for (int j = 0; j < 4; j++) {
            float lo, hi; unpack2(acc[i][j], lo, hi);
            o8[2 * j]     = wgt * lo;
            o8[2 * j + 1] = wgt * hi;
        }
        float4 x0 = *(const float4*)(Xr + (size_t)m * HW + tx * 8);
        float4 x1 = *(const float4*)(Xr + (size_t)m * HW + tx * 8 + 4);
        float4 r0, r1;
        r0.x = o8[0] + x0.x; r0.y = o8[1] + x0.y; r0.z = o8[2] + x0.z; r0.w = o8[3] + x0.w;
        r1.x = o8[4] + x1.x; r1.y = o8[5] + x1.y; r1.z = o8[6] + x1.z; r1.w = o8[7] + x1.w;
        *(float4*)(O + (size_t)m * HW + tx * 8)     = r0;
        *(float4*)(O + (size_t)m * HW + tx * 8 + 4) = r1;
    }
}

// ============================================================================
extern "C" void kernel_launch(void* const* d_in, const int* in_sizes, int n_in,
                              void* d_out, int out_size) {
    const float* x   = (const float*)d_in[0];
    const float* Wr1 = (const float*)d_in[1];
    const float* br1 = (const float*)d_in[2];
    const float* Wr2 = (const float*)d_in[3];
    const float* br2 = (const float*)d_in[4];
    const float* W1  = (const float*)d_in[5];
    const float* W2  = (const float*)d_in[6];
    const float* W3  = (const float*)d_in[7];
    float* out = (float*)d_out;

    pool_kernel  <<<BB * CC, 256>>>(x);
    router_kernel<<<BB, 128>>>(Wr1, br1, Wr2, br2);
    gemm1_kernel <<<dim3(32, BB), 256>>>(x, W1);
    conv3_kernel <<<dim3(16, 4, BB), 256>>>(W2);
    gemm3_kernel <<<dim3(32, 2, BB), 256>>>(x, W3, out);
}

// round 8
// speedup vs baseline: 1.4523x; 1.4523x over previous
#include <cuda_runtime.h>
#include <cstdint>

// Problem constants
#define BB  16
#define CC  256
#define HW  4096
#define EE  4
#define HID 128
#define RHD 128

// ---------------- device-global scratch (allowed; no dynamic alloc) ----------
__device__ __align__(16) float g_pooled[BB * CC];
__device__ int   g_expert[BB];
__device__ float g_weight[BB];
__device__ __align__(16) float g_y1[(size_t)BB * HID * HW];   // 32 MB
__device__ __align__(16) float g_y2[(size_t)BB * HID * HW];   // 32 MB

typedef unsigned long long u64;

// ---------------- packed f32x2 helpers (sm_100+ FFMA2) -----------------------
__device__ __forceinline__ u64 pack2(float lo, float hi) {
    u64 r; asm("mov.b64 %0, {%1, %2};" : "=l"(r) : "f"(lo), "f"(hi)); return r;
}
__device__ __forceinline__ void unpack2(u64 v, float& lo, float& hi) {
    asm("mov.b64 {%0, %1}, %2;" : "=f"(lo), "=f"(hi) : "l"(v));
}
__device__ __forceinline__ void fma2(u64& acc, u64 a, u64 b) {
    asm("fma.rn.f32x2 %0, %1, %2, %0;" : "+l"(acc) : "l"(a), "l"(b));
}
__device__ __forceinline__ float to_tf32(float x) {
    float r; asm("cvt.rna.tf32.f32 %0, %1;" : "=f"(r) : "f"(x)); return r;
}

// m16n8k8 tf32 mma (arch-agnostic PTX, works on plain sm_103 target)
__device__ __forceinline__ void mma_tf32(float* d,
                                         uint32_t a0, uint32_t a1, uint32_t a2, uint32_t a3,
                                         uint32_t b0, uint32_t b1) {
    asm volatile(
        "mma.sync.aligned.m16n8k8.row.col.f32.tf32.tf32.f32 "
        "{%0,%1,%2,%3}, {%4,%5,%6,%7}, {%8,%9}, {%0,%1,%2,%3};"
        : "+f"(d[0]), "+f"(d[1]), "+f"(d[2]), "+f"(d[3])
        : "r"(a0), "r"(a1), "r"(a2), "r"(a3), "r"(b0), "r"(b1));
}

// ============================================================================
// Kernel 1: global average pool.  grid = B*C blocks, 256 threads.
// ============================================================================
__global__ void pool_kernel(const float* __restrict__ x) {
    int bc = blockIdx.x;
    const float4* p = (const float4*)(x + (size_t)bc * HW);
    float s = 0.f;
    #pragma unroll
    for (int i = threadIdx.x; i < HW / 4; i += 256) {
        float4 v = p[i];
        s += (v.x + v.y) + (v.z + v.w);
    }
    __shared__ float red[8];
    #pragma unroll
    for (int o = 16; o > 0; o >>= 1) s += __shfl_down_sync(0xffffffffu, s, o);
    if ((threadIdx.x & 31) == 0) red[threadIdx.x >> 5] = s;
    __syncthreads();
    if (threadIdx.x < 8) {
        s = red[threadIdx.x];
        #pragma unroll
        for (int o = 4; o > 0; o >>= 1) s += __shfl_down_sync(0xffu, s, o);
        if (threadIdx.x == 0) g_pooled[bc] = s * (1.0f / (float)HW);
    }
}

// ============================================================================
// Kernel 2: router MLP + softmax + top-1.  grid = B, 128 threads.
// ============================================================================
__global__ void router_kernel(const float* __restrict__ Wr1, const float* __restrict__ br1,
                              const float* __restrict__ Wr2, const float* __restrict__ br2) {
    int b = blockIdx.x;
    int t = threadIdx.x;
    __shared__ float sp[CC];
    __shared__ float sh[RHD];
    __shared__ float slog[EE];
    sp[t]       = g_pooled[b * CC + t];
    sp[t + 128] = g_pooled[b * CC + t + 128];
    __syncthreads();
    {
        float acc = br1[t];
        const float* w = Wr1 + (size_t)t * CC;
        #pragma unroll 8
        for (int c = 0; c < CC; c++) acc = fmaf(sp[c], w[c], acc);
        sh[t] = fmaxf(acc, 0.f);
    }
    __syncthreads();
    if (t < EE) {
        float l = br2[t];
        const float* w = Wr2 + (size_t)t * RHD;
        #pragma unroll 8
        for (int r = 0; r < RHD; r++) l = fmaf(sh[r], w[r], l);
        slog[t] = l;
    }
    __syncthreads();
    if (t == 0) {
        float l0 = slog[0], l1 = slog[1], l2 = slog[2], l3 = slog[3];
        float m = fmaxf(fmaxf(l0, l1), fmaxf(l2, l3));
        float e0 = __expf(l0 - m), e1 = __expf(l1 - m), e2 = __expf(l2 - m), e3 = __expf(l3 - m);
        float s = e0 + e1 + e2 + e3;
        float p[4] = {e0 / s, e1 / s, e2 / s, e3 / s};
        int idx = 0; float v = p[0];
        #pragma unroll
        for (int i = 1; i < 4; i++) { if (p[i] > v) { v = p[i]; idx = i; } }
        g_expert[b] = idx;
        g_weight[b] = v / (v + 1e-9f);
    }
}

// ============================================================================
// Kernel 3: 1x1 conv C->HID with ReLU (GEMM M=128, N=4096, K=256 per batch).
// (known-good R3 scalar f32x2 version)
// ============================================================================
__global__ __launch_bounds__(256, 2) void gemm1_kernel(const float* __restrict__ x,
                                                       const float* __restrict__ W1) {
    __shared__ __align__(16) float As[16][128];   // [k][m]
    __shared__ __align__(16) float Bs[16][128];   // [k][n]
    int b  = blockIdx.y;
    int pt = blockIdx.x * 128;
    int e  = g_expert[b];
    const float* W = W1 + (size_t)e * (HID * CC);
    const float* X = x  + (size_t)b * CC * HW;

    u64 acc[8][4];
    #pragma unroll
    for (int i = 0; i < 8; i++)
        #pragma unroll
        for (int j = 0; j < 4; j++) acc[i][j] = 0ULL;

    int tid = threadIdx.x;
    int ty = tid >> 4, tx = tid & 15;
    int am = tid >> 1, ak = (tid & 1) << 3;
    int bk = tid >> 4, bn = (tid & 15) << 3;

    for (int kb = 0; kb < CC; kb += 16) {
        float4 a0 = *(const float4*)(W + (size_t)am * CC + kb + ak);
        float4 a1 = *(const float4*)(W + (size_t)am * CC + kb + ak + 4);
        float4 b0 = *(const float4*)(X + (size_t)(kb + bk) * HW + pt + bn);
        float4 b1 = *(const float4*)(X + (size_t)(kb + bk) * HW + pt + bn + 4);
        As[ak + 0][am] = a0.x; As[ak + 1][am] = a0.y; As[ak + 2][am] = a0.z; As[ak + 3][am] = a0.w;
        As[ak + 4][am] = a1.x; As[ak + 5][am] = a1.y; As[ak + 6][am] = a1.z; As[ak + 7][am] = a1.w;
        *(float4*)&Bs[bk][bn]     = b0;
        *(float4*)&Bs[bk][bn + 4] = b1;
        __syncthreads();
        #pragma unroll
        for (int k = 0; k < 16; k++) {
            float af[8];
            *(float4*)&af[0] = *(const float4*)&As[k][ty * 8];
            *(float4*)&af[4] = *(const float4*)&As[k][ty * 8 + 4];
            u64 bv[4];
            #pragma unroll
            for (int j = 0; j < 4; j++) bv[j] = *(const u64*)&Bs[k][tx * 8 + 2 * j];
            #pragma unroll
            for (int i = 0; i < 8; i++) {
                u64 av = pack2(af[i], af[i]);
                #pragma unroll
                for (int j = 0; j < 4; j++) fma2(acc[i][j], av, bv[j]);
            }
        }
        __syncthreads();
    }
    float* Y = g_y1 + (size_t)b * HID * HW + pt;
    #pragma unroll
    for (int i = 0; i < 8; i++) {
        float o8[8];
        #pragma unroll
        for (int j = 0; j < 4; j++) {
            float lo, hi; unpack2(acc[i][j], lo, hi);
            o8[2 * j]     = fmaxf(lo, 0.f);
            o8[2 * j + 1] = fmaxf(hi, 0.f);
        }
        float4* dst = (float4*)(Y + (size_t)(ty * 8 + i) * HW + tx * 8);
        dst[0] = *(float4*)&o8[0];
        dst[1] = *(float4*)&o8[4];
    }
}

// ============================================================================
// Kernel 4 (NEW): 3x3 conv HID->HID + ReLU as implicit GEMM on mma.sync tf32.
// Per CTA: D[128 oc][128 px] = sum_{k<1152} W'[oc][k] * B'[px][k], k=(ic,tap).
// SMEM tiles are stored in mma FRAGMENT order (built that way during im2col),
// so the inner loop is pure LDS.128/LDS.64 (conflict-free) + mma.
// 8 warps = 4(m) x 2(n); warp tile 32 oc x 64 px; K-chunk 32 (4 k-steps).
// grid = (32 pixel blocks, B), 256 threads.
// ============================================================================
__global__ __launch_bounds__(256) void conv3_mma_kernel(const float* __restrict__ W2) {
    // A frags: [8 mtiles][4 ksteps][32 lanes][4 regs]  (16 KB)
    // B frags: [16 ntiles][4 ksteps][32 lanes][2 regs] (16 KB)
    __shared__ __align__(16) float sA[8 * 4 * 32 * 4];
    __shared__ __align__(16) float sB[16 * 4 * 32 * 2];

    const int tid  = threadIdx.x;
    const int wid  = tid >> 5;
    const int lane = tid & 31;
    const int warpm = wid >> 1;          // 0..3  -> oc base = warpm*32
    const int warpn = wid & 1;           // 0..1  -> px base = warpn*64
    const int gid  = lane >> 2;          // fragment row group
    const int tig  = lane & 3;           // fragment thread-in-group

    int b  = blockIdx.y;
    int pb = blockIdx.x;                 // 0..31
    int pbase = pb << 7;                 // first pixel (2 image rows)
    int y0 = pb << 1;
    int e  = g_expert[b];
    const float* Wp = W2 + (size_t)e * (HID * HID * 9);   // [128][1152] row-major
    const float* Y1 = g_y1 + (size_t)b * HID * HW;

    float acc[2][8][4];
    #pragma unroll
    for (int i = 0; i < 2; i++)
        #pragma unroll
        for (int j = 0; j < 8; j++)
            #pragma unroll
            for (int r = 0; r < 4; r++) acc[i][j][r] = 0.f;

    for (int it = 0; it < 36; ++it) {
        int kb = it * 32;
        if (it) __syncthreads();   // previous compute done before overwrite
        // ---- build A tile [128 oc][32 k] directly into fragment order ----
        #pragma unroll 4
        for (int p = 0; p < 16; p++) {
            int idx = tid + (p << 8);            // 0..4095
            int m = idx >> 5, k = idx & 31;
            float v = to_tf32(__ldg(Wp + (size_t)m * 1152 + kb + k));
            int mt = m >> 4, ks = k >> 3;
            int fl = ((m & 7) << 2) | (k & 3);
            int rg = ((m >> 3) & 1) | (((k >> 2) & 1) << 1);
            sA[((((mt << 2) + ks) << 5) + fl) * 4 + rg] = v;
        }
        // ---- build B tile [32 k][128 px] via im2col into fragment order ----
        #pragma unroll 4
        for (int p = 0; p < 16; p++) {
            int idx = tid + (p << 8);            // 0..4095
            int n  = idx & 127, kk = idx >> 7;
            int k  = kb + kk;
            int ic  = k / 9;
            int tap = k - ic * 9;
            int ky  = tap / 3;
            int dx  = tap - ky * 3 - 1;
            int gy  = y0 + (n >> 6) + ky - 1;
            int gx  = (n & 63) + dx;
            float v = 0.f;
            if (((unsigned)gy < 64u) & ((unsigned)gx < 64u))
                v = __ldg(Y1 + (size_t)ic * HW + (gy << 6) + gx);
            int nt = n >> 3, ks = kk >> 3;
            int fl = ((n & 7) << 2) | (kk & 3);
            int rg = (kk >> 2) & 1;
            sB[((((nt << 2) + ks) << 5) + fl) * 2 + rg] = to_tf32(v);
        }
        __syncthreads();
        // ---- compute: 4 k-steps x (2 mtiles x 8 ntiles) mmas ----
        #pragma unroll
        for (int ks = 0; ks < 4; ks++) {
            uint32_t a[2][4];
            #pragma unroll
            for (int mt2 = 0; mt2 < 2; mt2++) {
                int mt = warpm * 2 + mt2;
                float4 t = *(const float4*)&sA[((((mt << 2) + ks) << 5) + lane) * 4];
                a[mt2][0] = __float_as_uint(t.x); a[mt2][1] = __float_as_uint(t.y);
                a[mt2][2] = __float_as_uint(t.z); a[mt2][3] = __float_as_uint(t.w);
            }
            #pragma unroll
            for (int nt2 = 0; nt2 < 8; nt2++) {
                int nt = warpn * 8 + nt2;
                float2 tb = *(const float2*)&sB[((((nt << 2) + ks) << 5) + lane) * 2];
                uint32_t b0 = __float_as_uint(tb.x);
                uint32_t b1 = __float_as_uint(tb.y);
                #pragma unroll
                for (int mt2 = 0; mt2 < 2; mt2++)
                    mma_tf32(acc[mt2][nt2], a[mt2][0], a[mt2][1], a[mt2][2], a[mt2][3], b0, b1);
            }
        }
    }

    // ---- epilogue: ReLU + store ----
    float* Y2 = g_y2 + (size_t)b * HID * HW;
    #pragma unroll
    for (int mt2 = 0; mt2 < 2; mt2++) {
        int oc0 = warpm * 32 + mt2 * 16 + gid;
        #pragma unroll
        for (int nt2 = 0; nt2 < 8; nt2++) {
            int px = pbase + warpn * 64 + nt2 * 8 + 2 * tig;
            float2 v0, v1;
            v0.x = fmaxf(acc[mt2][nt2][0], 0.f);
            v0.y = fmaxf(acc[mt2][nt2][1], 0.f);
            v1.x = fmaxf(acc[mt2][nt2][2], 0.f);
            v1.y = fmaxf(acc[mt2][nt2][3], 0.f);
            *(float2*)(Y2 + (size_t)oc0 * HW + px)       = v0;
            *(float2*)(Y2 + (size_t)(oc0 + 8) * HW + px) = v1;
        }
    }
}

// ============================================================================
// Kernel 5: 1x1 conv HID->C, scaled by routing weight, + residual.
// (known-good R3 scalar f32x2 version)
// ============================================================================
__global__ __launch_bounds__(256, 2) void gemm3_kernel(const float* __restrict__ x,
                                                       const float* __restrict__ W3,
                                                       float* __restrict__ out) {
    __shared__ __align__(16) float As[16][128];
    __shared__ __align__(16) float Bs[16][128];
    int b  = blockIdx.z;
    int m0 = blockIdx.y * 128;
    int pt = blockIdx.x * 128;
    int e  = g_expert[b];
    float wgt = g_weight[b];
    const float* W  = W3   + (size_t)e * (CC * HID) + (size_t)m0 * HID;
    const float* Y2 = g_y2 + (size_t)b * HID * HW;

    u64 acc[8][4];
    #pragma unroll
    for (int i = 0; i < 8; i++)
        #pragma unroll
        for (int j = 0; j < 4; j++) acc[i][j] = 0ULL;

    int tid = threadIdx.x;
    int ty = tid >> 4, tx = tid & 15;
    int am = tid >> 1, ak = (tid & 1) << 3;
    int bk = tid >> 4, bn = (tid & 15) << 3;

    for (int kb = 0; kb < HID; kb += 16) {
        float4 a0 = *(const float4*)(W + (size_t)am * HID + kb + ak);
        float4 a1 = *(const float4*)(W + (size_t)am * HID + kb + ak + 4);
        float4 b0 = *(const float4*)(Y2 + (size_t)(kb + bk) * HW + pt + bn);
        float4 b1 = *(const float4*)(Y2 + (size_t)(kb + bk) * HW + pt + bn + 4);
        As[ak + 0][am] = a0.x; As[ak + 1][am] = a0.y; As[ak + 2][am] = a0.z; As[ak + 3][am] = a0.w;
        As[ak + 4][am] = a1.x; As[ak + 5][am] = a1.y; As[ak + 6][am] = a1.z; As[ak + 7][am] = a1.w;
        *(float4*)&Bs[bk][bn]     = b0;
        *(float4*)&Bs[bk][bn + 4] = b1;
        __syncthreads();
        #pragma unroll
        for (int k = 0; k < 16; k++) {
            float af[8];
            *(float4*)&af[0] = *(const float4*)&As[k][ty * 8];
            *(float4*)&af[4] = *(const float4*)&As[k][ty * 8 + 4];
            u64 bv[4];
            #pragma unroll
            for (int j = 0; j < 4; j++) bv[j] = *(const u64*)&Bs[k][tx * 8 + 2 * j];
            #pragma unroll
            for (int i = 0; i < 8; i++) {
                u64 av = pack2(af[i], af[i]);
                #pragma unroll
                for (int j = 0; j < 4; j++) fma2(acc[i][j], av, bv[j]);
            }
        }
        __syncthreads();
    }
    const float* Xr = x   + (size_t)b * CC * HW + pt;
    float*       O  = out + (size_t)b * CC * HW + pt;
    #pragma unroll
    for (int i = 0; i < 8; i++) {
        int m = m0 + ty * 8 + i;
        float o8[8];
        #pragma unroll
        for (int j = 0; j < 4; j++) {
            float lo, hi; unpack2(acc[i][j], lo, hi);
            o8[2 * j]     = wgt * lo;
            o8[2 * j + 1] = wgt * hi;
        }
        float4 x0 = *(const float4*)(Xr + (size_t)m * HW + tx * 8);
        float4 x1 = *(const float4*)(Xr + (size_t)m * HW + tx * 8 + 4);
        float4 r0, r1;
        r0.x = o8[0] + x0.x; r0.y = o8[1] + x0.y; r0.z = o8[2] + x0.z; r0.w = o8[3] + x0.w;
        r1.x = o8[4] + x1.x; r1.y = o8[5] + x1.y; r1.z = o8[6] + x1.z; r1.w = o8[7] + x1.w;
        *(float4*)(O + (size_t)m * HW + tx * 8)     = r0;
        *(float4*)(O + (size_t)m * HW + tx * 8 + 4) = r1;
    }
}

// ============================================================================
extern "C" void kernel_launch(void* const* d_in, const int* in_sizes, int n_in,
                              void* d_out, int out_size) {
    const float* x   = (const float*)d_in[0];
    const float* Wr1 = (const float*)d_in[1];
    const float* br1 = (const float*)d_in[2];
    const float* Wr2 = (const float*)d_in[3];
    const float* br2 = (const float*)d_in[4];
    const float* W1  = (const float*)d_in[5];
    const float* W2  = (const float*)d_in[6];
    const float* W3  = (const float*)d_in[7];
    float* out = (float*)d_out;

    pool_kernel     <<<BB * CC, 256>>>(x);
    router_kernel   <<<BB, 128>>>(Wr1, br1, Wr2, br2);
    gemm1_kernel    <<<dim3(32, BB), 256>>>(x, W1);
    conv3_mma_kernel<<<dim3(32, BB), 256>>>(W2);
    gemm3_kernel    <<<dim3(32, 2, BB), 256>>>(x, W3, out);
}

// round 9
// speedup vs baseline: 2.0843x; 1.4352x over previous
#include <cuda_runtime.h>
#include <cstdint>

// Problem constants
#define BB  16
#define CC  256
#define HW  4096
#define EE  4
#define HID 128
#define RHD 128

// ---------------- device-global scratch (allowed; no dynamic alloc) ----------
__device__ __align__(16) float g_pooled[BB * CC];
__device__ int   g_expert[BB];
__device__ float g_weight[BB];
__device__ __align__(16) float g_y1[(size_t)BB * HID * HW];   // 32 MB
__device__ __align__(16) float g_y2[(size_t)BB * HID * HW];   // 32 MB

__device__ __forceinline__ float to_tf32(float x) {
    float r; asm("cvt.rna.tf32.f32 %0, %1;" : "=f"(r) : "f"(x)); return r;
}

// m16n8k8 tf32 mma (arch-agnostic PTX, works on plain sm_103 target)
__device__ __forceinline__ void mma_tf32(float* d,
                                         uint32_t a0, uint32_t a1, uint32_t a2, uint32_t a3,
                                         uint32_t b0, uint32_t b1) {
    asm volatile(
        "mma.sync.aligned.m16n8k8.row.col.f32.tf32.tf32.f32 "
        "{%0,%1,%2,%3}, {%4,%5,%6,%7}, {%8,%9}, {%0,%1,%2,%3};"
        : "+f"(d[0]), "+f"(d[1]), "+f"(d[2]), "+f"(d[3])
        : "r"(a0), "r"(a1), "r"(a2), "r"(a3), "r"(b0), "r"(b1));
}

// ============================================================================
// Shared tile geometry for all mma kernels.
// CTA tile 128m x 128n, K-chunk 32 (4 k-steps of 8).
// SMEM fragment layout:
//   sA[mt(8)][ks(4)][rg(4)][fl(32)]  addr = ((mt*4+ks)*4+rg)*32 + fl   (16 KB)
//   sB[nt(16)][ks(4)][rg(2)][fl(32)] addr = ((nt*4+ks)*2+rg)*32 + fl  (16 KB)
// A element (m,k): fl=(m&7)*4+(k&3), rg=((m>>3)&1)|(((k>>2)&1)<<1)
// B element (n,k): fl=(n&7)*4+(k&3), rg=(k>>2)&1
// Writer thread-mapping (q = tid + p*256, p<4):
//   low3 = tid&7 (m/n low), kq = (tid>>3)&7 -> k0 = kq*4, high = tid>>6 + 4p
//   m (or n) = high*8 + low3.  Each quad: one STS.128 (contiguous 128B per
//   8-lane phase -> conflict-free), A LDG.128 / B 4x coalesced scalar LDG.
// ============================================================================

struct WriterCtx {
    int k0;        // k offset within chunk (0,4,...,28)
    int mb;        // base m/n (p adds 32)
    int addrA0;    // A STS base (floats); +1024 per p
    int addrB0;    // B STS base (floats); +1024 per p
};

__device__ __forceinline__ WriterCtx make_ctx(int tid) {
    WriterCtx c;
    int low  = tid & 7;
    int kq   = (tid >> 3) & 7;
    int mh0  = tid >> 6;
    c.k0 = kq * 4;
    c.mb = mh0 * 8 + low;
    int mt0 = mh0 >> 1;
    int rgA = (mh0 & 1) | ((kq & 1) << 1);
    int ks  = kq >> 1;
    c.addrA0 = ((mt0 * 4 + ks) * 4 + rgA) * 32 + 4 * low;
    int rgB = kq & 1;
    c.addrB0 = ((mh0 * 4 + ks) * 2 + rgB) * 32 + 4 * low;
    return c;
}

__device__ __forceinline__ void sts_a(float* sA, const WriterCtx& c, const float4* pa) {
    #pragma unroll
    for (int p = 0; p < 4; p++) {
        float4 v = pa[p];
        v.x = to_tf32(v.x); v.y = to_tf32(v.y); v.z = to_tf32(v.z); v.w = to_tf32(v.w);
        *(float4*)(sA + c.addrA0 + 1024 * p) = v;
    }
}
__device__ __forceinline__ void sts_b(float* sB, const WriterCtx& c, const float pb[4][4]) {
    #pragma unroll
    for (int p = 0; p < 4; p++) {
        float4 v;
        v.x = to_tf32(pb[p][0]); v.y = to_tf32(pb[p][1]);
        v.z = to_tf32(pb[p][2]); v.w = to_tf32(pb[p][3]);
        *(float4*)(sB + c.addrB0 + 1024 * p) = v;
    }
}

// compute one K=32 chunk: 8 warps as 4(m)x2(n); warp = 32m x 64n
__device__ __forceinline__ void mma_chunk(const float* sA, const float* sB,
                                          int warpm, int warpn, int lane,
                                          float acc[2][8][4]) {
    #pragma unroll
    for (int ks = 0; ks < 4; ks++) {
        uint32_t a[2][4];
        #pragma unroll
        for (int mt2 = 0; mt2 < 2; mt2++) {
            const float* pa = sA + ((warpm * 2 + mt2) * 4 + ks) * 128 + lane;
            a[mt2][0] = __float_as_uint(pa[0]);
            a[mt2][1] = __float_as_uint(pa[32]);
            a[mt2][2] = __float_as_uint(pa[64]);
            a[mt2][3] = __float_as_uint(pa[96]);
        }
        #pragma unroll
        for (int nt2 = 0; nt2 < 8; nt2++) {
            const float* pb = sB + ((warpn * 8 + nt2) * 4 + ks) * 64 + lane;
            uint32_t b0 = __float_as_uint(pb[0]);
            uint32_t b1 = __float_as_uint(pb[32]);
            mma_tf32(acc[0][nt2], a[0][0], a[0][1], a[0][2], a[0][3], b0, b1);
            mma_tf32(acc[1][nt2], a[1][0], a[1][1], a[1][2], a[1][3], b0, b1);
        }
    }
}

// ============================================================================
// Kernel 1: global average pool.  grid = B*C blocks, 256 threads.
// ============================================================================
__global__ void pool_kernel(const float* __restrict__ x) {
    int bc = blockIdx.x;
    const float4* p = (const float4*)(x + (size_t)bc * HW);
    float s = 0.f;
    #pragma unroll
    for (int i = threadIdx.x; i < HW / 4; i += 256) {
        float4 v = p[i];
        s += (v.x + v.y) + (v.z + v.w);
    }
    __shared__ float red[8];
    #pragma unroll
    for (int o = 16; o > 0; o >>= 1) s += __shfl_down_sync(0xffffffffu, s, o);
    if ((threadIdx.x & 31) == 0) red[threadIdx.x >> 5] = s;
    __syncthreads();
    if (threadIdx.x < 8) {
        s = red[threadIdx.x];
        #pragma unroll
        for (int o = 4; o > 0; o >>= 1) s += __shfl_down_sync(0xffu, s, o);
        if (threadIdx.x == 0) g_pooled[bc] = s * (1.0f / (float)HW);
    }
}

// ============================================================================
// Kernel 2: router MLP + softmax + top-1.  grid = B, 128 threads.
// ============================================================================
__global__ void router_kernel(const float* __restrict__ Wr1, const float* __restrict__ br1,
                              const float* __restrict__ Wr2, const float* __restrict__ br2) {
    int b = blockIdx.x;
    int t = threadIdx.x;
    __shared__ float sp[CC];
    __shared__ float sh[RHD];
    __shared__ float slog[EE];
    sp[t]       = g_pooled[b * CC + t];
    sp[t + 128] = g_pooled[b * CC + t + 128];
    __syncthreads();
    {
        float acc = br1[t];
        const float* w = Wr1 + (size_t)t * CC;
        #pragma unroll 8
        for (int c = 0; c < CC; c++) acc = fmaf(sp[c], w[c], acc);
        sh[t] = fmaxf(acc, 0.f);
    }
    __syncthreads();
    if (t < EE) {
        float l = br2[t];
        const float* w = Wr2 + (size_t)t * RHD;
        #pragma unroll 8
        for (int r = 0; r < RHD; r++) l = fmaf(sh[r], w[r], l);
        slog[t] = l;
    }
    __syncthreads();
    if (t == 0) {
        float l0 = slog[0], l1 = slog[1], l2 = slog[2], l3 = slog[3];
        float m = fmaxf(fmaxf(l0, l1), fmaxf(l2, l3));
        float e0 = __expf(l0 - m), e1 = __expf(l1 - m), e2 = __expf(l2 - m), e3 = __expf(l3 - m);
        float s = e0 + e1 + e2 + e3;
        float p[4] = {e0 / s, e1 / s, e2 / s, e3 / s};
        int idx = 0; float v = p[0];
        #pragma unroll
        for (int i = 1; i < 4; i++) { if (p[i] > v) { v = p[i]; idx = i; } }
        g_expert[b] = idx;
        g_weight[b] = v / (v + 1e-9f);
    }
}

// ============================================================================
// Kernel 3: 1x1 conv C->HID + ReLU.  GEMM M=128, N=4096, K=256 (8 chunks).
// grid = (32 pixel tiles, B), 256 threads, tf32 mma pipeline.
// ============================================================================
__global__ __launch_bounds__(256, 2) void gemm1_mma_kernel(const float* __restrict__ x,
                                                           const float* __restrict__ W1) {
    __shared__ __align__(16) float sA[4096];
    __shared__ __align__(16) float sB[4096];
    const int tid  = threadIdx.x;
    const int wid  = tid >> 5;
    const int lane = tid & 31;
    const int warpm = wid >> 1, warpn = wid & 1;
    const int gid = lane >> 2, tig = lane & 3;

    int b  = blockIdx.y;
    int pt = blockIdx.x * 128;
    int e  = g_expert[b];
    const float* W = W1 + (size_t)e * (HID * CC);   // [128][256] row-major
    const float* X = x  + (size_t)b * CC * HW;      // [256][4096]

    WriterCtx c = make_ctx(tid);
    float acc[2][8][4];
    #pragma unroll
    for (int i = 0; i < 2; i++)
        #pragma unroll
        for (int j = 0; j < 8; j++)
            #pragma unroll
            for (int r = 0; r < 4; r++) acc[i][j][r] = 0.f;

    float4 pa[4];
    float  pb[4][4];
    // prologue: load chunk 0
    #pragma unroll
    for (int p = 0; p < 4; p++)
        pa[p] = *(const float4*)(W + (size_t)(c.mb + 32 * p) * CC + c.k0);
    #pragma unroll
    for (int j = 0; j < 4; j++) {
        const float* row = X + (size_t)(c.k0 + j) * HW + pt;
        #pragma unroll
        for (int p = 0; p < 4; p++) pb[p][j] = __ldg(row + c.mb + 32 * p);
    }

    for (int it = 0; it < 8; it++) {
        __syncthreads();
        sts_a(sA, c, pa);
        sts_b(sB, c, pb);
        __syncthreads();
        if (it + 1 < 8) {
            int kb = (it + 1) * 32;
            #pragma unroll
            for (int p = 0; p < 4; p++)
                pa[p] = *(const float4*)(W + (size_t)(c.mb + 32 * p) * CC + kb + c.k0);
            #pragma unroll
            for (int j = 0; j < 4; j++) {
                const float* row = X + (size_t)(kb + c.k0 + j) * HW + pt;
                #pragma unroll
                for (int p = 0; p < 4; p++) pb[p][j] = __ldg(row + c.mb + 32 * p);
            }
        }
        mma_chunk(sA, sB, warpm, warpn, lane, acc);
    }

    float* Y = g_y1 + (size_t)b * HID * HW;
    #pragma unroll
    for (int mt2 = 0; mt2 < 2; mt2++) {
        int oc0 = warpm * 32 + mt2 * 16 + gid;
        #pragma unroll
        for (int nt2 = 0; nt2 < 8; nt2++) {
            int px = pt + warpn * 64 + nt2 * 8 + 2 * tig;
            float2 v0, v1;
            v0.x = fmaxf(acc[mt2][nt2][0], 0.f);
            v0.y = fmaxf(acc[mt2][nt2][1], 0.f);
            v1.x = fmaxf(acc[mt2][nt2][2], 0.f);
            v1.y = fmaxf(acc[mt2][nt2][3], 0.f);
            *(float2*)(Y + (size_t)oc0 * HW + px)       = v0;
            *(float2*)(Y + (size_t)(oc0 + 8) * HW + px) = v1;
        }
    }
}

// ============================================================================
// Kernel 4: 3x3 conv HID->HID + ReLU, implicit GEMM, K=1152 (36 chunks).
// grid = (32 pixel blocks, B), 256 threads.
// ============================================================================
__global__ __launch_bounds__(256, 2) void conv3_mma_kernel(const float* __restrict__ W2) {
    __shared__ __align__(16) float sA[4096];
    __shared__ __align__(16) float sB[4096];
    const int tid  = threadIdx.x;
    const int wid  = tid >> 5;
    const int lane = tid & 31;
    const int warpm = wid >> 1, warpn = wid & 1;
    const int gid = lane >> 2, tig = lane & 3;

    int b  = blockIdx.y;
    int pb = blockIdx.x;
    int pbase = pb << 7;
    int y0 = pb << 1;
    int e  = g_expert[b];
    const float* Wp = W2 + (size_t)e * (HID * HID * 9);   // [128][1152] row-major
    const float* Y1 = g_y1 + (size_t)b * HID * HW;

    WriterCtx c = make_ctx(tid);
    // per-thread pixel info (n = c.mb + 32p)
    int nrow[4], ncol[4];
    #pragma unroll
    for (int p = 0; p < 4; p++) {
        int n = c.mb + 32 * p;
        nrow[p] = y0 + (n >> 6);
        ncol[p] = n & 63;
    }

    float acc[2][8][4];
    #pragma unroll
    for (int i = 0; i < 2; i++)
        #pragma unroll
        for (int j = 0; j < 8; j++)
            #pragma unroll
            for (int r = 0; r < 4; r++) acc[i][j][r] = 0.f;

    float4 pa[4];
    float  pbx[4][4];

    auto load_chunk = [&](int kb) {
        #pragma unroll
        for (int p = 0; p < 4; p++)
            pa[p] = *(const float4*)(Wp + (size_t)(c.mb + 32 * p) * 1152 + kb + c.k0);
        #pragma unroll
        for (int j = 0; j < 4; j++) {
            int k   = kb + c.k0 + j;
            int ic  = k / 9;
            int tap = k - ic * 9;
            int ky  = tap / 3;
            int dx  = tap - ky * 3 - 1;
            const float* src = Y1 + (size_t)ic * HW;
            #pragma unroll
            for (int p = 0; p < 4; p++) {
                int gy = nrow[p] + ky - 1;
                int gx = ncol[p] + dx;
                float v = 0.f;
                if (((unsigned)gy < 64u) & ((unsigned)gx < 64u))
                    v = __ldg(src + (gy << 6) + gx);
                pbx[p][j] = v;
            }
        }
    };

    load_chunk(0);
    for (int it = 0; it < 36; it++) {
        __syncthreads();
        sts_a(sA, c, pa);
        sts_b(sB, c, pbx);
        __syncthreads();
        if (it + 1 < 36) load_chunk((it + 1) * 32);
        mma_chunk(sA, sB, warpm, warpn, lane, acc);
    }

    float* Y2 = g_y2 + (size_t)b * HID * HW;
    #pragma unroll
    for (int mt2 = 0; mt2 < 2; mt2++) {
        int oc0 = warpm * 32 + mt2 * 16 + gid;
        #pragma unroll
        for (int nt2 = 0; nt2 < 8; nt2++) {
            int px = pbase + warpn * 64 + nt2 * 8 + 2 * tig;
            float2 v0, v1;
            v0.x = fmaxf(acc[mt2][nt2][0], 0.f);
            v0.y = fmaxf(acc[mt2][nt2][1], 0.f);
            v1.x = fmaxf(acc[mt2][nt2][2], 0.f);
            v1.y = fmaxf(acc[mt2][nt2][3], 0.f);
            *(float2*)(Y2 + (size_t)oc0 * HW + px)       = v0;
            *(float2*)(Y2 + (size_t)(oc0 + 8) * HW + px) = v1;
        }
    }
}

// ============================================================================
// Kernel 5: 1x1 conv HID->C * wgt + residual.  GEMM M=256, N=4096, K=128.
// grid = (32 pixel tiles, 2 m tiles, B), 256 threads.
// ============================================================================
__global__ __launch_bounds__(256, 2) void gemm3_mma_kernel(const float* __restrict__ x,
                                                           const float* __restrict__ W3,
                                                           float* __restrict__ out) {
    __shared__ __align__(16) float sA[4096];
    __shared__ __align__(16) float sB[4096];
    const int tid  = threadIdx.x;
    const int wid  = tid >> 5;
    const int lane = tid & 31;
    const int warpm = wid >> 1, warpn = wid & 1;
    const int gid = lane >> 2, tig = lane & 3;

    int b  = blockIdx.z;
    int m0 = blockIdx.y * 128;
    int pt = blockIdx.x * 128;
    int e  = g_expert[b];
    float wgt = g_weight[b];
    const float* W  = W3   + (size_t)e * (CC * HID) + (size_t)m0 * HID;   // [128][128]
    const float* Y2 = g_y2 + (size_t)b * HID * HW;

    WriterCtx c = make_ctx(tid);
    float acc[2][8][4];
    #pragma unroll
    for (int i = 0; i < 2; i++)
        #pragma unroll
        for (int j = 0; j < 8; j++)
            #pragma unroll
            for (int r = 0; r < 4; r++) acc[i][j][r] = 0.f;

    float4 pa[4];
    float  pb[4][4];
    #pragma unroll
    for (int p = 0; p < 4; p++)
        pa[p] = *(const float4*)(W + (size_t)(c.mb + 32 * p) * HID + c.k0);
    #pragma unroll
    for (int j = 0; j < 4; j++) {
        const float* row = Y2 + (size_t)(c.k0 + j) * HW + pt;
        #pragma unroll
        for (int p = 0; p < 4; p++) pb[p][j] = __ldg(row + c.mb + 32 * p);
    }

    for (int it = 0; it < 4; it++) {
        __syncthreads();
        sts_a(sA, c, pa);
        sts_b(sB, c, pb);
        __syncthreads();
        if (it + 1 < 4) {
            int kb = (it + 1) * 32;
            #pragma unroll
            for (int p = 0; p < 4; p++)
                pa[p] = *(const float4*)(W + (size_t)(c.mb + 32 * p) * HID + kb + c.k0);
            #pragma unroll
            for (int j = 0; j < 4; j++) {
                const float* row = Y2 + (size_t)(kb + c.k0 + j) * HW + pt;
                #pragma unroll
                for (int p = 0; p < 4; p++) pb[p][j] = __ldg(row + c.mb + 32 * p);
            }
        }
        mma_chunk(sA, sB, warpm, warpn, lane, acc);
    }

    const float* Xb = x   + (size_t)b * CC * HW;
    float*       O  = out + (size_t)b * CC * HW;
    #pragma unroll
    for (int mt2 = 0; mt2 < 2; mt2++) {
        int m_lo = m0 + warpm * 32 + mt2 * 16 + gid;
        int m_hi = m_lo + 8;
        #pragma unroll
        for (int nt2 = 0; nt2 < 8; nt2++) {
            int px = pt + warpn * 64 + nt2 * 8 + 2 * tig;
            float2 x0 = *(const float2*)(Xb + (size_t)m_lo * HW + px);
            float2 x1 = *(const float2*)(Xb + (size_t)m_hi * HW + px);
            float2 v0, v1;
            v0.x = fmaf(wgt, acc[mt2][nt2][0], x0.x);
            v0.y = fmaf(wgt, acc[mt2][nt2][1], x0.y);
            v1.x = fmaf(wgt, acc[mt2][nt2][2], x1.x);
            v1.y = fmaf(wgt, acc[mt2][nt2][3], x1.y);
            *(float2*)(O + (size_t)m_lo * HW + px) = v0;
            *(float2*)(O + (size_t)m_hi * HW + px) = v1;
        }
    }
}

// ============================================================================
extern "C" void kernel_launch(void* const* d_in, const int* in_sizes, int n_in,
                              void* d_out, int out_size) {
    const float* x   = (const float*)d_in[0];
    const float* Wr1 = (const float*)d_in[1];
    const float* br1 = (const float*)d_in[2];
    const float* Wr2 = (const float*)d_in[3];
    const float* br2 = (const float*)d_in[4];
    const float* W1  = (const float*)d_in[5];
    const float* W2  = (const float*)d_in[6];
    const float* W3  = (const float*)d_in[7];
    float* out = (float*)d_out;

    pool_kernel     <<<BB * CC, 256>>>(x);
    router_kernel   <<<BB, 128>>>(Wr1, br1, Wr2, br2);
    gemm1_mma_kernel<<<dim3(32, BB), 256>>>(x, W1);
    conv3_mma_kernel<<<dim3(32, BB), 256>>>(W2);
    gemm3_mma_kernel<<<dim3(32, 2, BB), 256>>>(x, W3, out);
}

// round 10
// speedup vs baseline: 2.3419x; 1.1236x over previous
#include <cuda_runtime.h>
#include <cstdint>

// Problem constants
#define BB  16
#define CC  256
#define HW  4096
#define EE  4
#define HID 128
#define RHD 128

// ---------------- device-global scratch (allowed; no dynamic alloc) ----------
__device__ __align__(16) float g_pooled[BB * CC];
__device__ int   g_expert[BB];
__device__ float g_weight[BB];
__device__ __align__(16) float g_y1[(size_t)BB * HID * HW];    // tf32-rounded
__device__ __align__(16) float g_y2[(size_t)BB * HID * HW];    // tf32-rounded
__device__ __align__(16) float g_xr[(size_t)BB * CC * HW];     // tf32-rounded x
__device__ __align__(16) float g_w1r[EE * HID * CC];
__device__ __align__(16) float g_w2r[EE * HID * HID * 9];
__device__ __align__(16) float g_w3r[EE * CC * HID];

__device__ __forceinline__ float to_tf32(float x) {
    float r; asm("cvt.rna.tf32.f32 %0, %1;" : "=f"(r) : "f"(x)); return r;
}

// m16n8k8 tf32 mma (arch-agnostic PTX, works on plain sm_103 target)
__device__ __forceinline__ void mma_tf32(float* d,
                                         uint32_t a0, uint32_t a1, uint32_t a2, uint32_t a3,
                                         uint32_t b0, uint32_t b1) {
    asm volatile(
        "mma.sync.aligned.m16n8k8.row.col.f32.tf32.tf32.f32 "
        "{%0,%1,%2,%3}, {%4,%5,%6,%7}, {%8,%9}, {%0,%1,%2,%3};"
        : "+f"(d[0]), "+f"(d[1]), "+f"(d[2]), "+f"(d[3])
        : "r"(a0), "r"(a1), "r"(a2), "r"(a3), "r"(b0), "r"(b1));
}

// ---------------- cp.async helpers ------------------------------------------
__device__ __forceinline__ uint32_t cvta_s(const void* p) {
    return (uint32_t)__cvta_generic_to_shared(p);
}
__device__ __forceinline__ void cp16(uint32_t dst, const void* src) {
    asm volatile("cp.async.cg.shared.global [%0], [%1], 16;" :: "r"(dst), "l"(src));
}
__device__ __forceinline__ void cp4(uint32_t dst, const void* src, uint32_t ssz) {
    asm volatile("cp.async.ca.shared.global [%0], [%1], 4, %2;" :: "r"(dst), "l"(src), "r"(ssz));
}
__device__ __forceinline__ void cp_commit()   { asm volatile("cp.async.commit_group;" ::: "memory"); }
__device__ __forceinline__ void cp_wait_all() { asm volatile("cp.async.wait_all;" ::: "memory"); }

// ============================================================================
// SMEM layouts per 32-K chunk (4096 floats each = 16 KB):
//  A word((m,k)) = ((mt*4+ks)*4 + rgA)*32 + (m&7)*4 + (k&3)
//      mt=m>>4, ks=k>>3, rgA=((m>>3)&1)|(((k>>2)&1)<<1)       [R9 layout]
//  B word((n,k)) = ((nt*4+ks)*2 + rg)*32 + (fl ^ swz(nt))
//      nt=n>>3, ks=k>>3, rg=(k>>2)&1, fl=(k&3)*8+(n&7)
//      GEMM swz = (nt&3)*8 (keeps 4-n 16B runs contiguous)
//      CONV swz = (nt&3) | ((nt&4)<<2)  (rank-5 => conflict-free 4B stores)
// Double buffer: buffer i at byte offset i*32768; B at +16384 within buffer.
// ============================================================================

template<int CONV>
__device__ __forceinline__ void mma_chunk(const float* sA, const float* sB,
                                          int warpm, int warpn, int lane,
                                          float acc[2][8][4]) {
    const int fl0 = (lane & 3) * 8 + (lane >> 2);
    #pragma unroll
    for (int ks = 0; ks < 4; ks++) {
        uint32_t a[2][4];
        #pragma unroll
        for (int mt2 = 0; mt2 < 2; mt2++) {
            const float* pa = sA + ((warpm * 2 + mt2) * 4 + ks) * 128 + lane;
            a[mt2][0] = __float_as_uint(pa[0]);
            a[mt2][1] = __float_as_uint(pa[32]);
            a[mt2][2] = __float_as_uint(pa[64]);
            a[mt2][3] = __float_as_uint(pa[96]);
        }
        #pragma unroll
        for (int nt2 = 0; nt2 < 8; nt2++) {
            int nt  = warpn * 8 + nt2;
            int swz = CONV ? ((nt & 3) | ((nt & 4) << 2)) : ((nt & 3) * 8);
            int fx  = fl0 ^ swz;
            const float* pb = sB + (nt * 4 + ks) * 64;
            uint32_t b0 = __float_as_uint(pb[fx]);
            uint32_t b1 = __float_as_uint(pb[32 + fx]);
            mma_tf32(acc[0][nt2], a[0][0], a[0][1], a[0][2], a[0][3], b0, b1);
            mma_tf32(acc[1][nt2], a[1][0], a[1][1], a[1][2], a[1][3], b0, b1);
        }
    }
}

// ============================================================================
// Kernel 1: global average pool + tf32-round x into g_xr. grid=B*C, 256 thr.
// ============================================================================
__global__ void pool_round_kernel(const float* __restrict__ x) {
    int bc = blockIdx.x;
    const float4* p = (const float4*)(x + (size_t)bc * HW);
    float4* q = (float4*)(g_xr + (size_t)bc * HW);
    float s = 0.f;
    #pragma unroll
    for (int i = threadIdx.x; i < HW / 4; i += 256) {
        float4 v = p[i];
        s += (v.x + v.y) + (v.z + v.w);
        float4 r;
        r.x = to_tf32(v.x); r.y = to_tf32(v.y); r.z = to_tf32(v.z); r.w = to_tf32(v.w);
        q[i] = r;
    }
    __shared__ float red[8];
    #pragma unroll
    for (int o = 16; o > 0; o >>= 1) s += __shfl_down_sync(0xffffffffu, s, o);
    if ((threadIdx.x & 31) == 0) red[threadIdx.x >> 5] = s;
    __syncthreads();
    if (threadIdx.x < 8) {
        s = red[threadIdx.x];
        #pragma unroll
        for (int o = 4; o > 0; o >>= 1) s += __shfl_down_sync(0xffu, s, o);
        if (threadIdx.x == 0) g_pooled[bc] = s * (1.0f / (float)HW);
    }
}

// generic tf32 rounding of weight arrays (float4 granularity)
__global__ void round_kernel(float* __restrict__ dst, const float* __restrict__ src, int n4) {
    int i = blockIdx.x * 256 + threadIdx.x;
    if (i < n4) {
        float4 v = ((const float4*)src)[i];
        float4 r;
        r.x = to_tf32(v.x); r.y = to_tf32(v.y); r.z = to_tf32(v.z); r.w = to_tf32(v.w);
        ((float4*)dst)[i] = r;
    }
}

// ============================================================================
// Kernel 2: router MLP + softmax + top-1.  grid = B, 128 threads.
// ============================================================================
__global__ void router_kernel(const float* __restrict__ Wr1, const float* __restrict__ br1,
                              const float* __restrict__ Wr2, const float* __restrict__ br2) {
    int b = blockIdx.x;
    int t = threadIdx.x;
    __shared__ float sp[CC];
    __shared__ float sh[RHD];
    __shared__ float slog[EE];
    sp[t]       = g_pooled[b * CC + t];
    sp[t + 128] = g_pooled[b * CC + t + 128];
    __syncthreads();
    {
        float acc = br1[t];
        const float* w = Wr1 + (size_t)t * CC;
        #pragma unroll 8
        for (int c = 0; c < CC; c++) acc = fmaf(sp[c], w[c], acc);
        sh[t] = fmaxf(acc, 0.f);
    }
    __syncthreads();
    if (t < EE) {
        float l = br2[t];
        const float* w = Wr2 + (size_t)t * RHD;
        #pragma unroll 8
        for (int r = 0; r < RHD; r++) l = fmaf(sh[r], w[r], l);
        slog[t] = l;
    }
    __syncthreads();
    if (t == 0) {
        float l0 = slog[0], l1 = slog[1], l2 = slog[2], l3 = slog[3];
        float m = fmaxf(fmaxf(l0, l1), fmaxf(l2, l3));
        float e0 = __expf(l0 - m), e1 = __expf(l1 - m), e2 = __expf(l2 - m), e3 = __expf(l3 - m);
        float s = e0 + e1 + e2 + e3;
        float p[4] = {e0 / s, e1 / s, e2 / s, e3 / s};
        int idx = 0; float v = p[0];
        #pragma unroll
        for (int i = 1; i < 4; i++) { if (p[i] > v) { v = p[i]; idx = i; } }
        g_expert[b] = idx;
        g_weight[b] = v / (v + 1e-9f);
    }
}

// ============================================================================
// Kernel 3: 1x1 conv C->HID + ReLU. GEMM M=128 N=4096 K=256 (8 chunks).
// cp.async double-buffered. grid=(32, B), 256 thr, 64KB dyn smem.
// ============================================================================
__global__ __launch_bounds__(256, 2) void gemm1_mma_kernel() {
    extern __shared__ float dsm[];
    const int tid = threadIdx.x, wid = tid >> 5, lane = tid & 31;
    const int warpm = wid >> 1, warpn = wid & 1;
    const int gid = lane >> 2, tig = lane & 3;
    int b  = blockIdx.y;
    int pt = blockIdx.x * 128;
    int e  = g_expert[b];
    const float* A  = g_w1r + (size_t)e * HID * CC;
    const float* Bx = g_xr  + (size_t)b * CC * HW + pt;

    // A writer ctx (R9)
    int low = tid & 7, kq = (tid >> 3) & 7, mh0 = tid >> 6;
    int ak0 = kq * 4, amb = mh0 * 8 + low;
    uint32_t wA0 = (((mh0 >> 1) * 4 + (kq >> 1)) * 4 + ((mh0 & 1) | ((kq & 1) << 1))) * 32 + 4 * low;
    // B writer ctx: kl = p*8+wid, nq = lane
    int nt_w = lane >> 1;
    uint32_t wBp[4];
    #pragma unroll
    for (int p = 0; p < 4; p++) {
        int kl = p * 8 + wid;
        wBp[p] = ((nt_w * 4 + (kl >> 3)) * 2 + ((kl >> 2) & 1)) * 32
               + (((kl & 3) ^ (nt_w & 3)) * 8) + (lane & 1) * 4;
    }
    uint32_t sm0 = cvta_s(dsm);

    float acc[2][8][4];
    #pragma unroll
    for (int i = 0; i < 2; i++)
        #pragma unroll
        for (int j = 0; j < 8; j++)
            #pragma unroll
            for (int r = 0; r < 4; r++) acc[i][j][r] = 0.f;

    // prologue load chunk 0
    #pragma unroll
    for (int p = 0; p < 4; p++)
        cp16(sm0 + (wA0 + 1024 * p) * 4, A + (size_t)(amb + 32 * p) * CC + ak0);
    #pragma unroll
    for (int p = 0; p < 4; p++)
        cp16(sm0 + 16384 + wBp[p] * 4, Bx + (size_t)(p * 8 + wid) * HW + lane * 4);
    cp_commit();

    for (int it = 0; it < 8; it++) {
        cp_wait_all();
        __syncthreads();
        if (it + 1 < 8) {
            int kb = (it + 1) * 32;
            uint32_t base = sm0 + ((it + 1) & 1) * 32768;
            #pragma unroll
            for (int p = 0; p < 4; p++)
                cp16(base + (wA0 + 1024 * p) * 4, A + (size_t)(amb + 32 * p) * CC + kb + ak0);
            #pragma unroll
            for (int p = 0; p < 4; p++)
                cp16(base + 16384 + wBp[p] * 4, Bx + (size_t)(kb + p * 8 + wid) * HW + lane * 4);
            cp_commit();
        }
        const float* sA = dsm + (it & 1) * 8192;
        mma_chunk<0>(sA, sA + 4096, warpm, warpn, lane, acc);
    }

    float* Y = g_y1 + (size_t)b * HID * HW;
    #pragma unroll
    for (int mt2 = 0; mt2 < 2; mt2++) {
        int oc0 = warpm * 32 + mt2 * 16 + gid;
        #pragma unroll
        for (int nt2 = 0; nt2 < 8; nt2++) {
            int px = pt + warpn * 64 + nt2 * 8 + 2 * tig;
            float2 v0, v1;
            v0.x = to_tf32(fmaxf(acc[mt2][nt2][0], 0.f));
            v0.y = to_tf32(fmaxf(acc[mt2][nt2][1], 0.f));
            v1.x = to_tf32(fmaxf(acc[mt2][nt2][2], 0.f));
            v1.y = to_tf32(fmaxf(acc[mt2][nt2][3], 0.f));
            *(float2*)(Y + (size_t)oc0 * HW + px)       = v0;
            *(float2*)(Y + (size_t)(oc0 + 8) * HW + px) = v1;
        }
    }
}

// ============================================================================
// Kernel 4: 3x3 conv HID->HID + ReLU, implicit GEMM, K=1152 (36 chunks).
// conv-B via predicated 4B cp.async (zero halo). grid=(32, B), 64KB smem.
// ============================================================================
__global__ __launch_bounds__(256, 2) void conv3_mma_kernel() {
    extern __shared__ float dsm[];
    const int tid = threadIdx.x, wid = tid >> 5, lane = tid & 31;
    const int warpm = wid >> 1, warpn = wid & 1;
    const int gid = lane >> 2, tig = lane & 3;
    int b  = blockIdx.y;
    int pb = blockIdx.x;
    int pbase = pb << 7;
    int y0 = pb << 1;
    int e  = g_expert[b];
    const float* A  = g_w2r + (size_t)e * (HID * HID * 9);  // [128][1152]
    const float* Y1 = g_y1 + (size_t)b * HID * HW;

    // A writer ctx
    int low = tid & 7, kq = (tid >> 3) & 7, mh0 = tid >> 6;
    int ak0 = kq * 4, amb = mh0 * 8 + low;
    uint32_t wA0 = (((mh0 >> 1) * 4 + (kq >> 1)) * 4 + ((mh0 & 1) | ((kq & 1) << 1))) * 32 + 4 * low;
    // conv B writer ctx: lanes span 16 nq x 2 k
    int nqL = lane & 15, kbit = lane >> 4;
    int klp[4], col0p[4], rowp[4], s01p[4];
    uint32_t wB0p[4];
    #pragma unroll
    for (int p = 0; p < 4; p++) {
        int kl = 2 * wid + kbit + 16 * (p & 1);
        int nq = nqL + 16 * (p >> 1);
        int n0 = nq * 4;
        int nt = nq >> 1;
        klp[p]   = kl;
        col0p[p] = n0 & 63;
        rowp[p]  = n0 >> 6;
        s01p[p]  = nt & 3;
        int fl0p = (kl & 3) * 8 + (nq & 1) * 4;
        wB0p[p]  = ((nt * 4 + (kl >> 3)) * 2 + ((kl >> 2) & 1)) * 32
                 + (fl0p ^ ((nt & 4) << 2));
    }
    uint32_t sm0 = cvta_s(dsm);

    float acc[2][8][4];
    #pragma unroll
    for (int i = 0; i < 2; i++)
        #pragma unroll
        for (int j = 0; j < 8; j++)
            #pragma unroll
            for (int r = 0; r < 4; r++) acc[i][j][r] = 0.f;

    auto load_chunk = [&](int kb, uint32_t base) {
        #pragma unroll
        for (int p = 0; p < 4; p++)
            cp16(base + (wA0 + 1024 * p) * 4, A + (size_t)(amb + 32 * p) * 1152 + kb + ak0);
        uint32_t bB = base + 16384;
        #pragma unroll
        for (int p = 0; p < 4; p++) {
            int k   = kb + klp[p];
            int ic  = k / 9;
            int tap = k - ic * 9;
            int ky  = tap / 3;
            int dx  = tap - ky * 3 - 1;
            int gy  = y0 + rowp[p] + ky - 1;
            bool vy = ((unsigned)gy < 64u);
            const float* srow = Y1 + (size_t)ic * HW + (gy << 6);
            #pragma unroll
            for (int j = 0; j < 4; j++) {
                int gx  = col0p[p] + j + dx;
                bool ok = vy & ((unsigned)gx < 64u);
                cp4(bB + (wB0p[p] + (j ^ s01p[p])) * 4, ok ? (srow + gx) : Y1, ok ? 4u : 0u);
            }
        }
    };

    load_chunk(0, sm0);
    cp_commit();
    for (int it = 0; it < 36; it++) {
        cp_wait_all();
        __syncthreads();
        if (it + 1 < 36) {
            load_chunk((it + 1) * 32, sm0 + ((it + 1) & 1) * 32768);
            cp_commit();
        }
        const float* sA = dsm + (it & 1) * 8192;
        mma_chunk<1>(sA, sA + 4096, warpm, warpn, lane, acc);
    }

    float* Y2 = g_y2 + (size_t)b * HID * HW;
    #pragma unroll
    for (int mt2 = 0; mt2 < 2; mt2++) {
        int oc0 = warpm * 32 + mt2 * 16 + gid;
        #pragma unroll
        for (int nt2 = 0; nt2 < 8; nt2++) {
            int px = pbase + warpn * 64 + nt2 * 8 + 2 * tig;
            float2 v0, v1;
            v0.x = to_tf32(fmaxf(acc[mt2][nt2][0], 0.f));
            v0.y = to_tf32(fmaxf(acc[mt2][nt2][1], 0.f));
            v1.x = to_tf32(fmaxf(acc[mt2][nt2][2], 0.f));
            v1.y = to_tf32(fmaxf(acc[mt2][nt2][3], 0.f));
            *(float2*)(Y2 + (size_t)oc0 * HW + px)       = v0;
            *(float2*)(Y2 + (size_t)(oc0 + 8) * HW + px) = v1;
        }
    }
}

// ============================================================================
// Kernel 5: 1x1 conv HID->C * wgt + residual. GEMM M=256 N=4096 K=128.
// grid = (32, 2, B), 256 thr, 64KB dyn smem.
// ============================================================================
__global__ __launch_bounds__(256, 2) void gemm3_mma_kernel(const float* __restrict__ x,
                                                           float* __restrict__ out) {
    extern __shared__ float dsm[];
    const int tid = threadIdx.x, wid = tid >> 5, lane = tid & 31;
    const int warpm = wid >> 1, warpn = wid & 1;
    const int gid = lane >> 2, tig = lane & 3;
    int b  = blockIdx.z;
    int m0 = blockIdx.y * 128;
    int pt = blockIdx.x * 128;
    int e  = g_expert[b];
    float wgt = g_weight[b];
    const float* A  = g_w3r + (size_t)e * (CC * HID) + (size_t)m0 * HID;
    const float* Bx = g_y2  + (size_t)b * HID * HW + pt;

    int low = tid & 7, kq = (tid >> 3) & 7, mh0 = tid >> 6;
    int ak0 = kq * 4, amb = mh0 * 8 + low;
    uint32_t wA0 = (((mh0 >> 1) * 4 + (kq >> 1)) * 4 + ((mh0 & 1) | ((kq & 1) << 1))) * 32 + 4 * low;
    int nt_w = lane >> 1;
    uint32_t wBp[4];
    #pragma unroll
    for (int p = 0; p < 4; p++) {
        int kl = p * 8 + wid;
        wBp[p] = ((nt_w * 4 + (kl >> 3)) * 2 + ((kl >> 2) & 1)) * 32
               + (((kl & 3) ^ (nt_w & 3)) * 8) + (lane & 1) * 4;
    }
    uint32_t sm0 = cvta_s(dsm);

    float acc[2][8][4];
    #pragma unroll
    for (int i = 0; i < 2; i++)
        #pragma unroll
        for (int j = 0; j < 8; j++)
            #pragma unroll
            for (int r = 0; r < 4; r++) acc[i][j][r] = 0.f;

    #pragma unroll
    for (int p = 0; p < 4; p++)
        cp16(sm0 + (wA0 + 1024 * p) * 4, A + (size_t)(amb + 32 * p) * HID + ak0);
    #pragma unroll
    for (int p = 0; p < 4; p++)
        cp16(sm0 + 16384 + wBp[p] * 4, Bx + (size_t)(p * 8 + wid) * HW + lane * 4);
    cp_commit();

    for (int it = 0; it < 4; it++) {
        cp_wait_all();
        __syncthreads();
        if (it + 1 < 4) {
            int kb = (it + 1) * 32;
            uint32_t base = sm0 + ((it + 1) & 1) * 32768;
            #pragma unroll
            for (int p = 0; p < 4; p++)
                cp16(base + (wA0 + 1024 * p) * 4, A + (size_t)(amb + 32 * p) * HID + kb + ak0);
            #pragma unroll
            for (int p = 0; p < 4; p++)
                cp16(base + 16384 + wBp[p] * 4, Bx + (size_t)(kb + p * 8 + wid) * HW + lane * 4);
            cp_commit();
        }
        const float* sA = dsm + (it & 1) * 8192;
        mma_chunk<0>(sA, sA + 4096, warpm, warpn, lane, acc);
    }

    const float* Xb = x   + (size_t)b * CC * HW;
    float*       O  = out + (size_t)b * CC * HW;
    #pragma unroll
    for (int mt2 = 0; mt2 < 2; mt2++) {
        int m_lo = m0 + warpm * 32 + mt2 * 16 + gid;
        int m_hi = m_lo + 8;
        #pragma unroll
        for (int nt2 = 0; nt2 < 8; nt2++) {
            int px = pt + warpn * 64 + nt2 * 8 + 2 * tig;
            float2 x0 = *(const float2*)(Xb + (size_t)m_lo * HW + px);
            float2 x1 = *(const float2*)(Xb + (size_t)m_hi * HW + px);
            float2 v0, v1;
            v0.x = fmaf(wgt, acc[mt2][nt2][0], x0.x);
            v0.y = fmaf(wgt, acc[mt2][nt2][1], x0.y);
            v1.x = fmaf(wgt, acc[mt2][nt2][2], x1.x);
            v1.y = fmaf(wgt, acc[mt2][nt2][3], x1.y);
            *(float2*)(O + (size_t)m_lo * HW + px) = v0;
            *(float2*)(O + (size_t)m_hi * HW + px) = v1;
        }
    }
}

// ============================================================================
extern "C" void kernel_launch(void* const* d_in, const int* in_sizes, int n_in,
                              void* d_out, int out_size) {
    const float* x   = (const float*)d_in[0];
    const float* Wr1 = (const float*)d_in[1];
    const float* br1 = (const float*)d_in[2];
    const float* Wr2 = (const float*)d_in[3];
    const float* br2 = (const float*)d_in[4];
    const float* W1  = (const float*)d_in[5];
    const float* W2  = (const float*)d_in[6];
    const float* W3  = (const float*)d_in[7];
    float* out = (float*)d_out;

    float* w1r; cudaGetSymbolAddress((void**)&w1r, g_w1r);
    float* w2r; cudaGetSymbolAddress((void**)&w2r, g_w2r);
    float* w3r; cudaGetSymbolAddress((void**)&w3r, g_w3r);

    cudaFuncSetAttribute(gemm1_mma_kernel, cudaFuncAttributeMaxDynamicSharedMemorySize, 65536);
    cudaFuncSetAttribute(conv3_mma_kernel, cudaFuncAttributeMaxDynamicSharedMemorySize, 65536);
    cudaFuncSetAttribute(gemm3_mma_kernel, cudaFuncAttributeMaxDynamicSharedMemorySize, 65536);

    pool_round_kernel<<<BB * CC, 256>>>(x);
    router_kernel    <<<BB, 128>>>(Wr1, br1, Wr2, br2);
    round_kernel     <<<128, 256>>>(w1r, W1, EE * HID * CC / 4);
    round_kernel     <<<576, 256>>>(w2r, W2, EE * HID * HID * 9 / 4);
    round_kernel     <<<128, 256>>>(w3r, W3, EE * CC * HID / 4);
    gemm1_mma_kernel <<<dim3(32, BB), 256, 65536>>>();
    conv3_mma_kernel <<<dim3(32, BB), 256, 65536>>>();
    gemm3_mma_kernel <<<dim3(32, 2, BB), 256, 65536>>>(x, out);
}

// round 11
// speedup vs baseline: 2.3710x; 1.0124x over previous
#include <cuda_runtime.h>
#include <cstdint>

// Problem constants
#define BB  16
#define CC  256
#define HW  4096
#define EE  4
#define HID 128
#define RHD 128

// ---------------- device-global scratch (allowed; no dynamic alloc) ----------
__device__ __align__(16) float g_pooled[BB * CC];
__device__ int   g_expert[BB];
__device__ float g_weight[BB];
__device__ __align__(16) float g_y1[(size_t)BB * HID * HW];    // tf32-rounded
__device__ __align__(16) float g_y2[(size_t)BB * HID * HW];    // tf32-rounded
__device__ __align__(16) float g_xr[(size_t)BB * CC * HW];     // tf32-rounded x
__device__ __align__(16) float g_w1r[EE * HID * CC];
__device__ __align__(16) float g_w2r[EE * HID * HID * 9];
__device__ __align__(16) float g_w3r[EE * CC * HID];

__device__ __forceinline__ float to_tf32(float x) {
    float r; asm("cvt.rna.tf32.f32 %0, %1;" : "=f"(r) : "f"(x)); return r;
}

// m16n8k8 tf32 mma (arch-agnostic PTX, works on plain sm_103 target)
__device__ __forceinline__ void mma_tf32(float* d,
                                         uint32_t a0, uint32_t a1, uint32_t a2, uint32_t a3,
                                         uint32_t b0, uint32_t b1) {
    asm volatile(
        "mma.sync.aligned.m16n8k8.row.col.f32.tf32.tf32.f32 "
        "{%0,%1,%2,%3}, {%4,%5,%6,%7}, {%8,%9}, {%0,%1,%2,%3};"
        : "+f"(d[0]), "+f"(d[1]), "+f"(d[2]), "+f"(d[3])
        : "r"(a0), "r"(a1), "r"(a2), "r"(a3), "r"(b0), "r"(b1));
}

// ---------------- cp.async helpers ------------------------------------------
__device__ __forceinline__ uint32_t cvta_s(const void* p) {
    return (uint32_t)__cvta_generic_to_shared(p);
}
__device__ __forceinline__ void cp16(uint32_t dst, const void* src) {
    asm volatile("cp.async.cg.shared.global [%0], [%1], 16;" :: "r"(dst), "l"(src));
}
__device__ __forceinline__ void cp4(uint32_t dst, const void* src, uint32_t ssz) {
    asm volatile("cp.async.ca.shared.global [%0], [%1], 4, %2;" :: "r"(dst), "l"(src), "r"(ssz));
}
__device__ __forceinline__ void cp_commit()   { asm volatile("cp.async.commit_group;" ::: "memory"); }
template<int N>
__device__ __forceinline__ void cp_wait_group() {
    asm volatile("cp.async.wait_group %0;" :: "n"(N) : "memory");
}

// ============================================================================
// SMEM layouts per 32-K chunk (4096 floats each = 16 KB):
//  A word((m,k)) = ((mt*4+ks)*4 + rgA)*32 + (m&7)*4 + (k&3)
//  B word((n,k)) = ((nt*4+ks)*2 + rg)*32 + (fl ^ swz(nt)),  fl=(k&3)*8+(n&7)
//      GEMM swz = (nt&3)*8 ;  CONV swz = (nt&3) | ((nt&4)<<2)
// Triple buffer: buffer i at byte offset i*32768; B at +16384 within buffer.
// ============================================================================

template<int CONV>
__device__ __forceinline__ void mma_chunk(const float* sA, const float* sB,
                                          int warpm, int warpn, int lane,
                                          float acc[2][8][4]) {
    const int fl0 = (lane & 3) * 8 + (lane >> 2);
    #pragma unroll
    for (int ks = 0; ks < 4; ks++) {
        uint32_t a[2][4];
        #pragma unroll
        for (int mt2 = 0; mt2 < 2; mt2++) {
            const float* pa = sA + ((warpm * 2 + mt2) * 4 + ks) * 128 + lane;
            a[mt2][0] = __float_as_uint(pa[0]);
            a[mt2][1] = __float_as_uint(pa[32]);
            a[mt2][2] = __float_as_uint(pa[64]);
            a[mt2][3] = __float_as_uint(pa[96]);
        }
        // software-pipelined B fragments (one nt ahead of the MMAs)
        auto ldb = [&](int nt2, uint32_t& b0, uint32_t& b1) {
            int nt  = warpn * 8 + nt2;
            int swz = CONV ? ((nt & 3) | ((nt & 4) << 2)) : ((nt & 3) * 8);
            int fx  = fl0 ^ swz;
            const float* pb = sB + (nt * 4 + ks) * 64;
            b0 = __float_as_uint(pb[fx]);
            b1 = __float_as_uint(pb[32 + fx]);
        };
        uint32_t b0c, b1c, b0n, b1n;
        ldb(0, b0c, b1c);
        #pragma unroll
        for (int nt2 = 0; nt2 < 8; nt2++) {
            if (nt2 < 7) ldb(nt2 + 1, b0n, b1n);
            mma_tf32(acc[0][nt2], a[0][0], a[0][1], a[0][2], a[0][3], b0c, b1c);
            mma_tf32(acc[1][nt2], a[1][0], a[1][1], a[1][2], a[1][3], b0c, b1c);
            b0c = b0n; b1c = b1n;
        }
    }
}

// ============================================================================
// Kernel 1: global average pool + tf32-round x into g_xr. grid=B*C, 256 thr.
// ============================================================================
__global__ void pool_round_kernel(const float* __restrict__ x) {
    int bc = blockIdx.x;
    const float4* p = (const float4*)(x + (size_t)bc * HW);
    float4* q = (float4*)(g_xr + (size_t)bc * HW);
    float s = 0.f;
    #pragma unroll
    for (int i = threadIdx.x; i < HW / 4; i += 256) {
        float4 v = p[i];
        s += (v.x + v.y) + (v.z + v.w);
        float4 r;
        r.x = to_tf32(v.x); r.y = to_tf32(v.y); r.z = to_tf32(v.z); r.w = to_tf32(v.w);
        q[i] = r;
    }
    __shared__ float red[8];
    #pragma unroll
    for (int o = 16; o > 0; o >>= 1) s += __shfl_down_sync(0xffffffffu, s, o);
    if ((threadIdx.x & 31) == 0) red[threadIdx.x >> 5] = s;
    __syncthreads();
    if (threadIdx.x < 8) {
        s = red[threadIdx.x];
        #pragma unroll
        for (int o = 4; o > 0; o >>= 1) s += __shfl_down_sync(0xffu, s, o);
        if (threadIdx.x == 0) g_pooled[bc] = s * (1.0f / (float)HW);
    }
}

// fused tf32 rounding of all three weight tensors (float4 granularity)
#define W1_F4 (EE * HID * CC / 4)
#define W2_F4 (EE * HID * HID * 9 / 4)
#define W3_F4 (EE * CC * HID / 4)
__global__ void round_all_kernel(const float* __restrict__ W1, const float* __restrict__ W2,
                                 const float* __restrict__ W3) {
    int i = blockIdx.x * 256 + threadIdx.x;
    const float4* src; float4* dst; int j;
    if (i < W1_F4)                 { src = (const float4*)W1; dst = (float4*)g_w1r; j = i; }
    else if (i < W1_F4 + W2_F4)    { src = (const float4*)W2; dst = (float4*)g_w2r; j = i - W1_F4; }
    else                           { src = (const float4*)W3; dst = (float4*)g_w3r; j = i - W1_F4 - W2_F4; }
    float4 v = src[j];
    float4 r;
    r.x = to_tf32(v.x); r.y = to_tf32(v.y); r.z = to_tf32(v.z); r.w = to_tf32(v.w);
    dst[j] = r;
}

// ============================================================================
// Kernel 2: router MLP + softmax + top-1.  grid = B, 128 threads.
// ============================================================================
__global__ void router_kernel(const float* __restrict__ Wr1, const float* __restrict__ br1,
                              const float* __restrict__ Wr2, const float* __restrict__ br2) {
    int b = blockIdx.x;
    int t = threadIdx.x;
    __shared__ float sp[CC];
    __shared__ float sh[RHD];
    __shared__ float slog[EE];
    sp[t]       = g_pooled[b * CC + t];
    sp[t + 128] = g_pooled[b * CC + t + 128];
    __syncthreads();
    {
        float acc = br1[t];
        const float* w = Wr1 + (size_t)t * CC;
        #pragma unroll 8
        for (int c = 0; c < CC; c++) acc = fmaf(sp[c], w[c], acc);
        sh[t] = fmaxf(acc, 0.f);
    }
    __syncthreads();
    if (t < EE) {
        float l = br2[t];
        const float* w = Wr2 + (size_t)t * RHD;
        #pragma unroll 8
        for (int r = 0; r < RHD; r++) l = fmaf(sh[r], w[r], l);
        slog[t] = l;
    }
    __syncthreads();
    if (t == 0) {
        float l0 = slog[0], l1 = slog[1], l2 = slog[2], l3 = slog[3];
        float m = fmaxf(fmaxf(l0, l1), fmaxf(l2, l3));
        float e0 = __expf(l0 - m), e1 = __expf(l1 - m), e2 = __expf(l2 - m), e3 = __expf(l3 - m);
        float s = e0 + e1 + e2 + e3;
        float p[4] = {e0 / s, e1 / s, e2 / s, e3 / s};
        int idx = 0; float v = p[0];
        #pragma unroll
        for (int i = 1; i < 4; i++) { if (p[i] > v) { v = p[i]; idx = i; } }
        g_expert[b] = idx;
        g_weight[b] = v / (v + 1e-9f);
    }
}

// ============================================================================
// Kernel 3: 1x1 conv C->HID + ReLU. GEMM M=128 N=4096 K=256 (8 chunks).
// 3-stage cp.async pipeline. grid=(32, B), 256 thr, 96KB dyn smem.
// ============================================================================
__global__ __launch_bounds__(256, 2) void gemm1_mma_kernel() {
    extern __shared__ float dsm[];
    const int tid = threadIdx.x, wid = tid >> 5, lane = tid & 31;
    const int warpm = wid >> 1, warpn = wid & 1;
    const int gid = lane >> 2, tig = lane & 3;
    int b  = blockIdx.y;
    int pt = blockIdx.x * 128;
    int e  = g_expert[b];
    const float* A  = g_w1r + (size_t)e * HID * CC;
    const float* Bx = g_xr  + (size_t)b * CC * HW + pt;

    int low = tid & 7, kq = (tid >> 3) & 7, mh0 = tid >> 6;
    int ak0 = kq * 4, amb = mh0 * 8 + low;
    uint32_t wA0 = (((mh0 >> 1) * 4 + (kq >> 1)) * 4 + ((mh0 & 1) | ((kq & 1) << 1))) * 32 + 4 * low;
    int nt_w = lane >> 1;
    uint32_t wBp[4];
    #pragma unroll
    for (int p = 0; p < 4; p++) {
        int kl = p * 8 + wid;
        wBp[p] = ((nt_w * 4 + (kl >> 3)) * 2 + ((kl >> 2) & 1)) * 32
               + (((kl & 3) ^ (nt_w & 3)) * 8) + (lane & 1) * 4;
    }
    uint32_t sm0 = cvta_s(dsm);

    float acc[2][8][4];
    #pragma unroll
    for (int i = 0; i < 2; i++)
        #pragma unroll
        for (int j = 0; j < 8; j++)
            #pragma unroll
            for (int r = 0; r < 4; r++) acc[i][j][r] = 0.f;

    auto load_chunk = [&](int kb, uint32_t base) {
        #pragma unroll
        for (int p = 0; p < 4; p++)
            cp16(base + (wA0 + 1024 * p) * 4, A + (size_t)(amb + 32 * p) * CC + kb + ak0);
        #pragma unroll
        for (int p = 0; p < 4; p++)
            cp16(base + 16384 + wBp[p] * 4, Bx + (size_t)(kb + p * 8 + wid) * HW + lane * 4);
    };

    load_chunk(0, sm0);       cp_commit();
    load_chunk(32, sm0 + 32768); cp_commit();

    int cur = 0, pf = 2;
    for (int it = 0; it < 8; it++) {
        cp_wait_group<1>();
        __syncthreads();
        if (it + 2 < 8) load_chunk((it + 2) * 32, sm0 + pf * 32768);
        cp_commit();     // empty group at the tail keeps wait_group semantics
        const float* sA = dsm + cur * 8192;
        mma_chunk<0>(sA, sA + 4096, warpm, warpn, lane, acc);
        cur = (cur == 2) ? 0 : cur + 1;
        pf  = (pf  == 2) ? 0 : pf  + 1;
    }

    float* Y = g_y1 + (size_t)b * HID * HW;
    #pragma unroll
    for (int mt2 = 0; mt2 < 2; mt2++) {
        int oc0 = warpm * 32 + mt2 * 16 + gid;
        #pragma unroll
        for (int nt2 = 0; nt2 < 8; nt2++) {
            int px = pt + warpn * 64 + nt2 * 8 + 2 * tig;
            float2 v0, v1;
            v0.x = to_tf32(fmaxf(acc[mt2][nt2][0], 0.f));
            v0.y = to_tf32(fmaxf(acc[mt2][nt2][1], 0.f));
            v1.x = to_tf32(fmaxf(acc[mt2][nt2][2], 0.f));
            v1.y = to_tf32(fmaxf(acc[mt2][nt2][3], 0.f));
            *(float2*)(Y + (size_t)oc0 * HW + px)       = v0;
            *(float2*)(Y + (size_t)(oc0 + 8) * HW + px) = v1;
        }
    }
}

// ============================================================================
// Kernel 4: 3x3 conv HID->HID + ReLU, implicit GEMM, K=1152 (36 chunks).
// 3-stage cp.async pipeline. grid=(32, B), 256 thr, 96KB dyn smem.
// ============================================================================
__global__ __launch_bounds__(256, 2) void conv3_mma_kernel() {
    extern __shared__ float dsm[];
    const int tid = threadIdx.x, wid = tid >> 5, lane = tid & 31;
    const int warpm = wid >> 1, warpn = wid & 1;
    const int gid = lane >> 2, tig = lane & 3;
    int b  = blockIdx.y;
    int pb = blockIdx.x;
    int pbase = pb << 7;
    int y0 = pb << 1;
    int e  = g_expert[b];
    const float* A  = g_w2r + (size_t)e * (HID * HID * 9);  // [128][1152]
    const float* Y1 = g_y1 + (size_t)b * HID * HW;

    int low = tid & 7, kq = (tid >> 3) & 7, mh0 = tid >> 6;
    int ak0 = kq * 4, amb = mh0 * 8 + low;
    uint32_t wA0 = (((mh0 >> 1) * 4 + (kq >> 1)) * 4 + ((mh0 & 1) | ((kq & 1) << 1))) * 32 + 4 * low;
    int nqL = lane & 15, kbit = lane >> 4;
    int klp[4], col0p[4], rowp[4], s01p[4];
    uint32_t wB0p[4];
    #pragma unroll
    for (int p = 0; p < 4; p++) {
        int kl = 2 * wid + kbit + 16 * (p & 1);
        int nq = nqL + 16 * (p >> 1);
        int n0 = nq * 4;
        int nt = nq >> 1;
        klp[p]   = kl;
        col0p[p] = n0 & 63;
        rowp[p]  = n0 >> 6;
        s01p[p]  = nt & 3;
        int fl0p = (kl & 3) * 8 + (nq & 1) * 4;
        wB0p[p]  = ((nt * 4 + (kl >> 3)) * 2 + ((kl >> 2) & 1)) * 32
                 + (fl0p ^ ((nt & 4) << 2));
    }
    uint32_t sm0 = cvta_s(dsm);

    float acc[2][8][4];
    #pragma unroll
    for (int i = 0; i < 2; i++)
        #pragma unroll
        for (int j = 0; j < 8; j++)
            #pragma unroll
            for (int r = 0; r < 4; r++) acc[i][j][r] = 0.f;

    auto load_chunk = [&](int kb, uint32_t base) {
        #pragma unroll
        for (int p = 0; p < 4; p++)
            cp16(base + (wA0 + 1024 * p) * 4, A + (size_t)(amb + 32 * p) * 1152 + kb + ak0);
        uint32_t bB = base + 16384;
        #pragma unroll
        for (int p = 0; p < 4; p++) {
            int k   = kb + klp[p];
            int ic  = k / 9;
            int tap = k - ic * 9;
            int ky  = tap / 3;
            int dx  = tap - ky * 3 - 1;
            int gy  = y0 + rowp[p] + ky - 1;
            bool vy = ((unsigned)gy < 64u);
            const float* srow = Y1 + (size_t)ic * HW + (gy << 6);
            #pragma unroll
            for (int j = 0; j < 4; j++) {
                int gx  = col0p[p] + j + dx;
                bool ok = vy & ((unsigned)gx < 64u);
                cp4(bB + (wB0p[p] + (j ^ s01p[p])) * 4, ok ? (srow + gx) : Y1, ok ? 4u : 0u);
            }
        }
    };

    load_chunk(0, sm0);          cp_commit();
    load_chunk(32, sm0 + 32768); cp_commit();

    int cur = 0, pf = 2;
    for (int it = 0; it < 36; it++) {
        cp_wait_group<1>();
        __syncthreads();
        if (it + 2 < 36) load_chunk((it + 2) * 32, sm0 + pf * 32768);
        cp_commit();
        const float* sA = dsm + cur * 8192;
        mma_chunk<1>(sA, sA + 4096, warpm, warpn, lane, acc);
        cur = (cur == 2) ? 0 : cur + 1;
        pf  = (pf  == 2) ? 0 : pf  + 1;
    }

    float* Y2 = g_y2 + (size_t)b * HID * HW;
    #pragma unroll
    for (int mt2 = 0; mt2 < 2; mt2++) {
        int oc0 = warpm * 32 + mt2 * 16 + gid;
        #pragma unroll
        for (int nt2 = 0; nt2 < 8; nt2++) {
            int px = pbase + warpn * 64 + nt2 * 8 + 2 * tig;
            float2 v0, v1;
            v0.x = to_tf32(fmaxf(acc[mt2][nt2][0], 0.f));
            v0.y = to_tf32(fmaxf(acc[mt2][nt2][1], 0.f));
            v1.x = to_tf32(fmaxf(acc[mt2][nt2][2], 0.f));
            v1.y = to_tf32(fmaxf(acc[mt2][nt2][3], 0.f));
            *(float2*)(Y2 + (size_t)oc0 * HW + px)       = v0;
            *(float2*)(Y2 + (size_t)(oc0 + 8) * HW + px) = v1;
        }
    }
}

// ============================================================================
// Kernel 5: 1x1 conv HID->C * wgt + residual. GEMM M=256 N=4096 K=128.
// 3-stage cp.async pipeline. grid=(32, 2, B), 256 thr, 96KB dyn smem.
// ============================================================================
__global__ __launch_bounds__(256, 2) void gemm3_mma_kernel(const float* __restrict__ x,
                                                           float* __restrict__ out) {
    extern __shared__ float dsm[];
    const int tid = threadIdx.x, wid = tid >> 5, lane = tid & 31;
    const int warpm = wid >> 1, warpn = wid & 1;
    const int gid = lane >> 2, tig = lane & 3;
    int b  = blockIdx.z;
    int m0 = blockIdx.y * 128;
    int pt = blockIdx.x * 128;
    int e  = g_expert[b];
    float wgt = g_weight[b];
    const float* A  = g_w3r + (size_t)e * (CC * HID) + (size_t)m0 * HID;
    const float* Bx = g_y2  + (size_t)b * HID * HW + pt;

    int low = tid & 7, kq = (tid >> 3) & 7, mh0 = tid >> 6;
    int ak0 = kq * 4, amb = mh0 * 8 + low;
    uint32_t wA0 = (((mh0 >> 1) * 4 + (kq >> 1)) * 4 + ((mh0 & 1) | ((kq & 1) << 1))) * 32 + 4 * low;
    int nt_w = lane >> 1;
    uint32_t wBp[4];
    #pragma unroll
    for (int p = 0; p < 4; p++) {
        int kl = p * 8 + wid;
        wBp[p] = ((nt_w * 4 + (kl >> 3)) * 2 + ((kl >> 2) & 1)) * 32
               + (((kl & 3) ^ (nt_w & 3)) * 8) + (lane & 1) * 4;
    }
    uint32_t sm0 = cvta_s(dsm);

    float acc[2][8][4];
    #pragma unroll
    for (int i = 0; i < 2; i++)
        #pragma unroll
        for (int j = 0; j < 8; j++)
            #pragma unroll
            for (int r = 0; r < 4; r++) acc[i][j][r] = 0.f;

    auto load_chunk = [&](int kb, uint32_t base) {
        #pragma unroll
        for (int p = 0; p < 4; p++)
            cp16(base + (wA0 + 1024 * p) * 4, A + (size_t)(amb + 32 * p) * HID + kb + ak0);
        #pragma unroll
        for (int p = 0; p < 4; p++)
            cp16(base + 16384 + wBp[p] * 4, Bx + (size_t)(kb + p * 8 + wid) * HW + lane * 4);
    };

    load_chunk(0, sm0);          cp_commit();
    load_chunk(32, sm0 + 32768); cp_commit();

    int cur = 0, pf = 2;
    for (int it = 0; it < 4; it++) {
        cp_wait_group<1>();
        __syncthreads();
        if (it + 2 < 4) load_chunk((it + 2) * 32, sm0 + pf * 32768);
        cp_commit();
        const float* sA = dsm + cur * 8192;
        mma_chunk<0>(sA, sA + 4096, warpm, warpn, lane, acc);
        cur = (cur == 2) ? 0 : cur + 1;
        pf  = (pf  == 2) ? 0 : pf  + 1;
    }

    const float* Xb = x   + (size_t)b * CC * HW;
    float*       O  = out + (size_t)b * CC * HW;
    #pragma unroll
    for (int mt2 = 0; mt2 < 2; mt2++) {
        int m_lo = m0 + warpm * 32 + mt2 * 16 + gid;
        int m_hi = m_lo + 8;
        #pragma unroll
        for (int nt2 = 0; nt2 < 8; nt2++) {
            int px = pt + warpn * 64 + nt2 * 8 + 2 * tig;
            float2 x0 = *(const float2*)(Xb + (size_t)m_lo * HW + px);
            float2 x1 = *(const float2*)(Xb + (size_t)m_hi * HW + px);
            float2 v0, v1;
            v0.x = fmaf(wgt, acc[mt2][nt2][0], x0.x);
            v0.y = fmaf(wgt, acc[mt2][nt2][1], x0.y);
            v1.x = fmaf(wgt, acc[mt2][nt2][2], x1.x);
            v1.y = fmaf(wgt, acc[mt2][nt2][3], x1.y);
            *(float2*)(O + (size_t)m_lo * HW + px) = v0;
            *(float2*)(O + (size_t)m_hi * HW + px) = v1;
        }
    }
}

// ============================================================================
extern "C" void kernel_launch(void* const* d_in, const int* in_sizes, int n_in,
                              void* d_out, int out_size) {
    const float* x   = (const float*)d_in[0];
    const float* Wr1 = (const float*)d_in[1];
    const float* br1 = (const float*)d_in[2];
    const float* Wr2 = (const float*)d_in[3];
    const float* br2 = (const float*)d_in[4];
    const float* W1  = (const float*)d_in[5];
    const float* W2  = (const float*)d_in[6];
    const float* W3  = (const float*)d_in[7];
    float* out = (float*)d_out;

    cudaFuncSetAttribute(gemm1_mma_kernel, cudaFuncAttributeMaxDynamicSharedMemorySize, 98304);
    cudaFuncSetAttribute(conv3_mma_kernel, cudaFuncAttributeMaxDynamicSharedMemorySize, 98304);
    cudaFuncSetAttribute(gemm3_mma_kernel, cudaFuncAttributeMaxDynamicSharedMemorySize, 98304);

    pool_round_kernel<<<BB * CC, 256>>>(x);
    round_all_kernel <<<(W1_F4 + W2_F4 + W3_F4 + 255) / 256, 256>>>(W1, W2, W3);
    router_kernel    <<<BB, 128>>>(Wr1, br1, Wr2, br2);
    gemm1_mma_kernel <<<dim3(32, BB), 256, 98304>>>();
    conv3_mma_kernel <<<dim3(32, BB), 256, 98304>>>();
    gemm3_mma_kernel <<<dim3(32, 2, BB), 256, 98304>>>(x, out);
}

// round 12
// speedup vs baseline: 2.3816x; 1.0045x over previous
#include <cuda_runtime.h>
#include <cstdint>

// Problem constants
#define BB  16
#define CC  256
#define HW  4096
#define EE  4
#define HID 128
#define RHD 128

// ---------------- device-global scratch (allowed; no dynamic alloc) ----------
__device__ __align__(16) float g_pooled[BB * CC];
__device__ int   g_expert[BB];
__device__ float g_weight[BB];
__device__ __align__(16) float g_y1[(size_t)BB * HID * HW];    // tf32-rounded
__device__ __align__(16) float g_y2[(size_t)BB * HID * HW];    // tf32-rounded
__device__ __align__(16) float g_xr[(size_t)BB * CC * HW];     // tf32-rounded x
__device__ __align__(16) float g_w1r[EE * HID * CC];
__device__ __align__(16) float g_w2r[EE * HID * HID * 9];
__device__ __align__(16) float g_w3r[EE * CC * HID];

__device__ __forceinline__ float to_tf32(float x) {
    float r; asm("cvt.rna.tf32.f32 %0, %1;" : "=f"(r) : "f"(x)); return r;
}

// m16n8k8 tf32 mma (arch-agnostic PTX, works on plain sm_103 target)
__device__ __forceinline__ void mma_tf32(float* d,
                                         uint32_t a0, uint32_t a1, uint32_t a2, uint32_t a3,
                                         uint32_t b0, uint32_t b1) {
    asm volatile(
        "mma.sync.aligned.m16n8k8.row.col.f32.tf32.tf32.f32 "
        "{%0,%1,%2,%3}, {%4,%5,%6,%7}, {%8,%9}, {%0,%1,%2,%3};"
        : "+f"(d[0]), "+f"(d[1]), "+f"(d[2]), "+f"(d[3])
        : "r"(a0), "r"(a1), "r"(a2), "r"(a3), "r"(b0), "r"(b1));
}

// ---------------- cp.async helpers ------------------------------------------
__device__ __forceinline__ uint32_t cvta_s(const void* p) {
    return (uint32_t)__cvta_generic_to_shared(p);
}
__device__ __forceinline__ void cp16(uint32_t dst, const void* src) {
    asm volatile("cp.async.cg.shared.global [%0], [%1], 16;" :: "r"(dst), "l"(src));
}
__device__ __forceinline__ void cp4(uint32_t dst, const void* src, uint32_t ssz) {
    asm volatile("cp.async.ca.shared.global [%0], [%1], 4, %2;" :: "r"(dst), "l"(src), "r"(ssz));
}
__device__ __forceinline__ void cp_commit()   { asm volatile("cp.async.commit_group;" ::: "memory"); }
template<int N>
__device__ __forceinline__ void cp_wait_group() {
    asm volatile("cp.async.wait_group %0;" :: "n"(N) : "memory");
}

// ============================================================================
// SMEM layouts per 32-K chunk (4096 floats each = 16 KB):
//  A word((m,k)) = ((mt*4+ks)*4 + rgA)*32 + (m&7)*4 + (k&3)
//  B word((n,k)) = ((nt*4+ks)*2 + rg)*32 + (fl ^ swz(nt)),  fl=(k&3)*8+(n&7)
//      GEMM swz = (nt&3)*8 ;  CONV swz = (nt&3) | ((nt&4)<<2)
// Triple buffer: buffer i at byte offset i*32768; B at +16384 within buffer.
// ============================================================================

template<int CONV>
__device__ __forceinline__ void mma_chunk(const float* sA, const float* sB,
                                          int warpm, int warpn, int lane,
                                          float acc[2][8][4]) {
    const int fl0 = (lane & 3) * 8 + (lane >> 2);
    #pragma unroll
    for (int ks = 0; ks < 4; ks++) {
        uint32_t a[2][4];
        #pragma unroll
        for (int mt2 = 0; mt2 < 2; mt2++) {
            const float* pa = sA + ((warpm * 2 + mt2) * 4 + ks) * 128 + lane;
            a[mt2][0] = __float_as_uint(pa[0]);
            a[mt2][1] = __float_as_uint(pa[32]);
            a[mt2][2] = __float_as_uint(pa[64]);
            a[mt2][3] = __float_as_uint(pa[96]);
        }
        // software-pipelined B fragments (one nt ahead of the MMAs)
        auto ldb = [&](int nt2, uint32_t& b0, uint32_t& b1) {
            int nt  = warpn * 8 + nt2;
            int swz = CONV ? ((nt & 3) | ((nt & 4) << 2)) : ((nt & 3) * 8);
            int fx  = fl0 ^ swz;
            const float* pb = sB + (nt * 4 + ks) * 64;
            b0 = __float_as_uint(pb[fx]);
            b1 = __float_as_uint(pb[32 + fx]);
        };
        uint32_t b0c, b1c, b0n, b1n;
        ldb(0, b0c, b1c);
        #pragma unroll
        for (int nt2 = 0; nt2 < 8; nt2++) {
            if (nt2 < 7) ldb(nt2 + 1, b0n, b1n);
            mma_tf32(acc[0][nt2], a[0][0], a[0][1], a[0][2], a[0][3], b0c, b1c);
            mma_tf32(acc[1][nt2], a[1][0], a[1][1], a[1][2], a[1][3], b0c, b1c);
            b0c = b0n; b1c = b1n;
        }
    }
}

// ============================================================================
// Kernel 1: global average pool + tf32-round x into g_xr. grid=B*C, 256 thr.
// ============================================================================
__global__ void pool_round_kernel(const float* __restrict__ x) {
    int bc = blockIdx.x;
    const float4* p = (const float4*)(x + (size_t)bc * HW);
    float4* q = (float4*)(g_xr + (size_t)bc * HW);
    float s = 0.f;
    #pragma unroll
    for (int i = threadIdx.x; i < HW / 4; i += 256) {
        float4 v = p[i];
        s += (v.x + v.y) + (v.z + v.w);
        float4 r;
        r.x = to_tf32(v.x); r.y = to_tf32(v.y); r.z = to_tf32(v.z); r.w = to_tf32(v.w);
        q[i] = r;
    }
    __shared__ float red[8];
    #pragma unroll
    for (int o = 16; o > 0; o >>= 1) s += __shfl_down_sync(0xffffffffu, s, o);
    if ((threadIdx.x & 31) == 0) red[threadIdx.x >> 5] = s;
    __syncthreads();
    if (threadIdx.x < 8) {
        s = red[threadIdx.x];
        #pragma unroll
        for (int o = 4; o > 0; o >>= 1) s += __shfl_down_sync(0xffu, s, o);
        if (threadIdx.x == 0) g_pooled[bc] = s * (1.0f / (float)HW);
    }
}

// fused tf32 rounding of all three weight tensors (float4 granularity)
#define W1_F4 (EE * HID * CC / 4)
#define W2_F4 (EE * HID * HID * 9 / 4)
#define W3_F4 (EE * CC * HID / 4)
__global__ void round_all_kernel(const float* __restrict__ W1, const float* __restrict__ W2,
                                 const float* __restrict__ W3) {
    int i = blockIdx.x * 256 + threadIdx.x;
    const float4* src; float4* dst; int j;
    if (i < W1_F4)                 { src = (const float4*)W1; dst = (float4*)g_w1r; j = i; }
    else if (i < W1_F4 + W2_F4)    { src = (const float4*)W2; dst = (float4*)g_w2r; j = i - W1_F4; }
    else                           { src = (const float4*)W3; dst = (float4*)g_w3r; j = i - W1_F4 - W2_F4; }
    float4 v = src[j];
    float4 r;
    r.x = to_tf32(v.x); r.y = to_tf32(v.y); r.z = to_tf32(v.z); r.w = to_tf32(v.w);
    dst[j] = r;
}

// ============================================================================
// Kernel 2: router MLP + softmax + top-1.  grid = B, 128 threads.
// ============================================================================
__global__ void router_kernel(const float* __restrict__ Wr1, const float* __restrict__ br1,
                              const float* __restrict__ Wr2, const float* __restrict__ br2) {
    int b = blockIdx.x;
    int t = threadIdx.x;
    __shared__ float sp[CC];
    __shared__ float sh[RHD];
    __shared__ float slog[EE];
    sp[t]       = g_pooled[b * CC + t];
    sp[t + 128] = g_pooled[b * CC + t + 128];
    __syncthreads();
    {
        float acc = br1[t];
        const float* w = Wr1 + (size_t)t * CC;
        #pragma unroll 8
        for (int c = 0; c < CC; c++) acc = fmaf(sp[c], w[c], acc);
        sh[t] = fmaxf(acc, 0.f);
    }
    __syncthreads();
    if (t < EE) {
        float l = br2[t];
        const float* w = Wr2 + (size_t)t * RHD;
        #pragma unroll 8
        for (int r = 0; r < RHD; r++) l = fmaf(sh[r], w[r], l);
        slog[t] = l;
    }
    __syncthreads();
    if (t == 0) {
        float l0 = slog[0], l1 = slog[1], l2 = slog[2], l3 = slog[3];
        float m = fmaxf(fmaxf(l0, l1), fmaxf(l2, l3));
        float e0 = __expf(l0 - m), e1 = __expf(l1 - m), e2 = __expf(l2 - m), e3 = __expf(l3 - m);
        float s = e0 + e1 + e2 + e3;
        float p[4] = {e0 / s, e1 / s, e2 / s, e3 / s};
        int idx = 0; float v = p[0];
        #pragma unroll
        for (int i = 1; i < 4; i++) { if (p[i] > v) { v = p[i]; idx = i; } }
        g_expert[b] = idx;
        g_weight[b] = v / (v + 1e-9f);
    }
}

// ============================================================================
// Kernel 3: 1x1 conv C->HID + ReLU. GEMM M=128 N=4096 K=256 (8 chunks).
// 3-stage cp.async pipeline. grid=(32, B), 256 thr, 96KB dyn smem.
// ============================================================================
__global__ __launch_bounds__(256, 2) void gemm1_mma_kernel() {
    extern __shared__ float dsm[];
    const int tid = threadIdx.x, wid = tid >> 5, lane = tid & 31;
    const int warpm = wid >> 1, warpn = wid & 1;
    const int gid = lane >> 2, tig = lane & 3;
    int b  = blockIdx.y;
    int pt = blockIdx.x * 128;
    int e  = g_expert[b];
    const float* A  = g_w1r + (size_t)e * HID * CC;
    const float* Bx = g_xr  + (size_t)b * CC * HW + pt;

    int low = tid & 7, kq = (tid >> 3) & 7, mh0 = tid >> 6;
    int ak0 = kq * 4, amb = mh0 * 8 + low;
    uint32_t wA0 = (((mh0 >> 1) * 4 + (kq >> 1)) * 4 + ((mh0 & 1) | ((kq & 1) << 1))) * 32 + 4 * low;
    int nt_w = lane >> 1;
    uint32_t wBp[4];
    #pragma unroll
    for (int p = 0; p < 4; p++) {
        int kl = p * 8 + wid;
        wBp[p] = ((nt_w * 4 + (kl >> 3)) * 2 + ((kl >> 2) & 1)) * 32
               + (((kl & 3) ^ (nt_w & 3)) * 8) + (lane & 1) * 4;
    }
    uint32_t sm0 = cvta_s(dsm);

    float acc[2][8][4];
    #pragma unroll
    for (int i = 0; i < 2; i++)
        #pragma unroll
        for (int j = 0; j < 8; j++)
            #pragma unroll
            for (int r = 0; r < 4; r++) acc[i][j][r] = 0.f;

    auto load_chunk = [&](int kb, uint32_t base) {
        #pragma unroll
        for (int p = 0; p < 4; p++)
            cp16(base + (wA0 + 1024 * p) * 4, A + (size_t)(amb + 32 * p) * CC + kb + ak0);
        #pragma unroll
        for (int p = 0; p < 4; p++)
            cp16(base + 16384 + wBp[p] * 4, Bx + (size_t)(kb + p * 8 + wid) * HW + lane * 4);
    };

    load_chunk(0, sm0);       cp_commit();
    load_chunk(32, sm0 + 32768); cp_commit();

    int cur = 0, pf = 2;
    for (int it = 0; it < 8; it++) {
        cp_wait_group<1>();
        __syncthreads();
        if (it + 2 < 8) load_chunk((it + 2) * 32, sm0 + pf * 32768);
        cp_commit();     // empty group at the tail keeps wait_group semantics
        const float* sA = dsm + cur * 8192;
        mma_chunk<0>(sA, sA + 4096, warpm, warpn, lane, acc);
        cur = (cur == 2) ? 0 : cur + 1;
        pf  = (pf  == 2) ? 0 : pf  + 1;
    }

    float* Y = g_y1 + (size_t)b * HID * HW;
    #pragma unroll
    for (int mt2 = 0; mt2 < 2; mt2++) {
        int oc0 = warpm * 32 + mt2 * 16 + gid;
        #pragma unroll
        for (int nt2 = 0; nt2 < 8; nt2++) {
            int px = pt + warpn * 64 + nt2 * 8 + 2 * tig;
            float2 v0, v1;
            v0.x = to_tf32(fmaxf(acc[mt2][nt2][0], 0.f));
            v0.y = to_tf32(fmaxf(acc[mt2][nt2][1], 0.f));
            v1.x = to_tf32(fmaxf(acc[mt2][nt2][2], 0.f));
            v1.y = to_tf32(fmaxf(acc[mt2][nt2][3], 0.f));
            *(float2*)(Y + (size_t)oc0 * HW + px)       = v0;
            *(float2*)(Y + (size_t)(oc0 + 8) * HW + px) = v1;
        }
    }
}

// ============================================================================
// Kernel 4: 3x3 conv HID->HID + ReLU, implicit GEMM, K=1152 (36 chunks).
// 3-stage cp.async pipeline. grid=(32, B), 256 thr, 96KB dyn smem.
// ============================================================================
__global__ __launch_bounds__(256, 2) void conv3_mma_kernel() {
    extern __shared__ float dsm[];
    const int tid = threadIdx.x, wid = tid >> 5, lane = tid & 31;
    const int warpm = wid >> 1, warpn = wid & 1;
    const int gid = lane >> 2, tig = lane & 3;
    int b  = blockIdx.y;
    int pb = blockIdx.x;
    int pbase = pb << 7;
    int y0 = pb << 1;
    int e  = g_expert[b];
    const float* A  = g_w2r + (size_t)e * (HID * HID * 9);  // [128][1152]
    const float* Y1 = g_y1 + (size_t)b * HID * HW;

    int low = tid & 7, kq = (tid >> 3) & 7, mh0 = tid >> 6;
    int ak0 = kq * 4, amb = mh0 * 8 + low;
    uint32_t wA0 = (((mh0 >> 1) * 4 + (kq >> 1)) * 4 + ((mh0 & 1) | ((kq & 1) << 1))) * 32 + 4 * low;
    int nqL = lane & 15, kbit = lane >> 4;
    int klp[4], col0p[4], rowp[4], s01p[4];
    uint32_t wB0p[4];
    #pragma unroll
    for (int p = 0; p < 4; p++) {
        int kl = 2 * wid + kbit + 16 * (p & 1);
        int nq = nqL + 16 * (p >> 1);
        int n0 = nq * 4;
        int nt = nq >> 1;
        klp[p]   = kl;
        col0p[p] = n0 & 63;
        rowp[p]  = n0 >> 6;
        s01p[p]  = nt & 3;
        int fl0p = (kl & 3) * 8 + (nq & 1) * 4;
        wB0p[p]  = ((nt * 4 + (kl >> 3)) * 2 + ((kl >> 2) & 1)) * 32
                 + (fl0p ^ ((nt & 4) << 2));
    }
    uint32_t sm0 = cvta_s(dsm);

    float acc[2][8][4];
    #pragma unroll
    for (int i = 0; i < 2; i++)
        #pragma unroll
        for (int j = 0; j < 8; j++)
            #pragma unroll
            for (int r = 0; r < 4; r++) acc[i][j][r] = 0.f;

    auto load_chunk = [&](int kb, uint32_t base) {
        #pragma unroll
        for (int p = 0; p < 4; p++)
            cp16(base + (wA0 + 1024 * p) * 4, A + (size_t)(amb + 32 * p) * 1152 + kb + ak0);
        uint32_t bB = base + 16384;
        #pragma unroll
        for (int p = 0; p < 4; p++) {
            int k   = kb + klp[p];
            int ic  = k / 9;
            int tap = k - ic * 9;
            int ky  = tap / 3;
            int dx  = tap - ky * 3 - 1;
            int gy  = y0 + rowp[p] + ky - 1;
            bool vy = ((unsigned)gy < 64u);
            const float* srow = Y1 + (size_t)ic * HW + (gy << 6);
            #pragma unroll
            for (int j = 0; j < 4; j++) {
                int gx  = col0p[p] + j + dx;
                bool ok = vy & ((unsigned)gx < 64u);
                cp4(bB + (wB0p[p] + (j ^ s01p[p])) * 4, ok ? (srow + gx) : Y1, ok ? 4u : 0u);
            }
        }
    };

    load_chunk(0, sm0);          cp_commit();
    load_chunk(32, sm0 + 32768); cp_commit();

    int cur = 0, pf = 2;
    for (int it = 0; it < 36; it++) {
        cp_wait_group<1>();
        __syncthreads();
        if (it + 2 < 36) load_chunk((it + 2) * 32, sm0 + pf * 32768);
        cp_commit();
        const float* sA = dsm + cur * 8192;
        mma_chunk<1>(sA, sA + 4096, warpm, warpn, lane, acc);
        cur = (cur == 2) ? 0 : cur + 1;
        pf  = (pf  == 2) ? 0 : pf  + 1;
    }

    float* Y2 = g_y2 + (size_t)b * HID * HW;
    #pragma unroll
    for (int mt2 = 0; mt2 < 2; mt2++) {
        int oc0 = warpm * 32 + mt2 * 16 + gid;
        #pragma unroll
        for (int nt2 = 0; nt2 < 8; nt2++) {
            int px = pbase + warpn * 64 + nt2 * 8 + 2 * tig;
            float2 v0, v1;
            v0.x = to_tf32(fmaxf(acc[mt2][nt2][0], 0.f));
            v0.y = to_tf32(fmaxf(acc[mt2][nt2][1], 0.f));
            v1.x = to_tf32(fmaxf(acc[mt2][nt2][2], 0.f));
            v1.y = to_tf32(fmaxf(acc[mt2][nt2][3], 0.f));
            *(float2*)(Y2 + (size_t)oc0 * HW + px)       = v0;
            *(float2*)(Y2 + (size_t)(oc0 + 8) * HW + px) = v1;
        }
    }
}

// ============================================================================
// Kernel 5: 1x1 conv HID->C * wgt + residual. GEMM M=256 N=4096 K=128.
// 3-stage cp.async pipeline. grid=(32, 2, B), 256 thr, 96KB dyn smem.
// ============================================================================
__global__ __launch_bounds__(256, 2) void gemm3_mma_kernel(const float* __restrict__ x,
                                                           float* __restrict__ out) {
    extern __shared__ float dsm[];
    const int tid = threadIdx.x, wid = tid >> 5, lane = tid & 31;
    const int warpm = wid >> 1, warpn = wid & 1;
    const int gid = lane >> 2, tig = lane & 3;
    int b  = blockIdx.z;
    int m0 = blockIdx.y * 128;
    int pt = blockIdx.x * 128;
    int e  = g_expert[b];
    float wgt = g_weight[b];
    const float* A  = g_w3r + (size_t)e * (CC * HID) + (size_t)m0 * HID;
    const float* Bx = g_y2  + (size_t)b * HID * HW + pt;

    int low = tid & 7, kq = (tid >> 3) & 7, mh0 = tid >> 6;
    int ak0 = kq * 4, amb = mh0 * 8 + low;
    uint32_t wA0 = (((mh0 >> 1) * 4 + (kq >> 1)) * 4 + ((mh0 & 1) | ((kq & 1) << 1))) * 32 + 4 * low;
    int nt_w = lane >> 1;
    uint32_t wBp[4];
    #pragma unroll
    for (int p = 0; p < 4; p++) {
        int kl = p * 8 + wid;
        wBp[p] = ((nt_w * 4 + (kl >> 3)) * 2 + ((kl >> 2) & 1)) * 32
               + (((kl & 3) ^ (nt_w & 3)) * 8) + (lane & 1) * 4;
    }
    uint32_t sm0 = cvta_s(dsm);

    float acc[2][8][4];
    #pragma unroll
    for (int i = 0; i < 2; i++)
        #pragma unroll
        for (int j = 0; j < 8; j++)
            #pragma unroll
            for (int r = 0; r < 4; r++) acc[i][j][r] = 0.f;

    auto load_chunk = [&](int kb, uint32_t base) {
        #pragma unroll
        for (int p = 0; p < 4; p++)
            cp16(base + (wA0 + 1024 * p) * 4, A + (size_t)(amb + 32 * p) * HID + kb + ak0);
        #pragma unroll
        for (int p = 0; p < 4; p++)
            cp16(base + 16384 + wBp[p] * 4, Bx + (size_t)(kb + p * 8 + wid) * HW + lane * 4);
    };

    load_chunk(0, sm0);          cp_commit();
    load_chunk(32, sm0 + 32768); cp_commit();

    int cur = 0, pf = 2;
    for (int it = 0; it < 4; it++) {
        cp_wait_group<1>();
        __syncthreads();
        if (it + 2 < 4) load_chunk((it + 2) * 32, sm0 + pf * 32768);
        cp_commit();
        const float* sA = dsm + cur * 8192;
        mma_chunk<0>(sA, sA + 4096, warpm, warpn, lane, acc);
        cur = (cur == 2) ? 0 : cur + 1;
        pf  = (pf  == 2) ? 0 : pf  + 1;
    }

    const float* Xb = x   + (size_t)b * CC * HW;
    float*       O  = out + (size_t)b * CC * HW;
    #pragma unroll
    for (int mt2 = 0; mt2 < 2; mt2++) {
        int m_lo = m0 + warpm * 32 + mt2 * 16 + gid;
        int m_hi = m_lo + 8;
        #pragma unroll
        for (int nt2 = 0; nt2 < 8; nt2++) {
            int px = pt + warpn * 64 + nt2 * 8 + 2 * tig;
            float2 x0 = *(const float2*)(Xb + (size_t)m_lo * HW + px);
            float2 x1 = *(const float2*)(Xb + (size_t)m_hi * HW + px);
            float2 v0, v1;
            v0.x = fmaf(wgt, acc[mt2][nt2][0], x0.x);
            v0.y = fmaf(wgt, acc[mt2][nt2][1], x0.y);
            v1.x = fmaf(wgt, acc[mt2][nt2][2], x1.x);
            v1.y = fmaf(wgt, acc[mt2][nt2][3], x1.y);
            *(float2*)(O + (size_t)m_lo * HW + px) = v0;
            *(float2*)(O + (size_t)m_hi * HW + px) = v1;
        }
    }
}

// ============================================================================
extern "C" void kernel_launch(void* const* d_in, const int* in_sizes, int n_in,
                              void* d_out, int out_size) {
    const float* x   = (const float*)d_in[0];
    const float* Wr1 = (const float*)d_in[1];
    const float* br1 = (const float*)d_in[2];
    const float* Wr2 = (const float*)d_in[3];
    const float* br2 = (const float*)d_in[4];
    const float* W1  = (const float*)d_in[5];
    const float* W2  = (const float*)d_in[6];
    const float* W3  = (const float*)d_in[7];
    float* out = (float*)d_out;

    cudaFuncSetAttribute(gemm1_mma_kernel, cudaFuncAttributeMaxDynamicSharedMemorySize, 98304);
    cudaFuncSetAttribute(conv3_mma_kernel, cudaFuncAttributeMaxDynamicSharedMemorySize, 98304);
    cudaFuncSetAttribute(gemm3_mma_kernel, cudaFuncAttributeMaxDynamicSharedMemorySize, 98304);

    pool_round_kernel<<<BB * CC, 256>>>(x);
    round_all_kernel <<<(W1_F4 + W2_F4 + W3_F4 + 255) / 256, 256>>>(W1, W2, W3);
    router_kernel    <<<BB, 128>>>(Wr1, br1, Wr2, br2);
    gemm1_mma_kernel <<<dim3(32, BB), 256, 98304>>>();
    conv3_mma_kernel <<<dim3(32, BB), 256, 98304>>>();
    gemm3_mma_kernel <<<dim3(32, 2, BB), 256, 98304>>>(x, out);
}

// round 13
// speedup vs baseline: 2.3841x; 1.0011x over previous
#include <cuda_runtime.h>
#include <cstdint>

// Problem constants
#define BB  16
#define CC  256
#define HW  4096
#define EE  4
#define HID 128
#define RHD 128

// ---------------- device-global scratch (allowed; no dynamic alloc) ----------
__device__ __align__(16) float g_pooled[BB * CC];
__device__ int   g_expert[BB];
__device__ float g_weight[BB];
__device__ __align__(16) float g_y1[(size_t)BB * HID * HW];    // tf32-rounded
__device__ __align__(16) float g_y2[(size_t)BB * HID * HW];    // tf32-rounded
__device__ __align__(16) float g_xr[(size_t)BB * CC * HW];     // tf32-rounded x
__device__ __align__(16) float g_w1r[EE * HID * CC];
__device__ __align__(16) float g_w2r[EE * HID * HID * 9];
__device__ __align__(16) float g_w3r[EE * CC * HID];

__device__ __forceinline__ float to_tf32(float x) {
    float r; asm("cvt.rna.tf32.f32 %0, %1;" : "=f"(r) : "f"(x)); return r;
}

// m16n8k8 tf32 mma (arch-agnostic PTX, works on plain sm_103 target)
__device__ __forceinline__ void mma_tf32(float* d,
                                         uint32_t a0, uint32_t a1, uint32_t a2, uint32_t a3,
                                         uint32_t b0, uint32_t b1) {
    asm volatile(
        "mma.sync.aligned.m16n8k8.row.col.f32.tf32.tf32.f32 "
        "{%0,%1,%2,%3}, {%4,%5,%6,%7}, {%8,%9}, {%0,%1,%2,%3};"
        : "+f"(d[0]), "+f"(d[1]), "+f"(d[2]), "+f"(d[3])
        : "r"(a0), "r"(a1), "r"(a2), "r"(a3), "r"(b0), "r"(b1));
}

// ---------------- cp.async helpers ------------------------------------------
__device__ __forceinline__ uint32_t cvta_s(const void* p) {
    return (uint32_t)__cvta_generic_to_shared(p);
}
__device__ __forceinline__ void cp16(uint32_t dst, const void* src) {
    asm volatile("cp.async.cg.shared.global [%0], [%1], 16;" :: "r"(dst), "l"(src));
}
__device__ __forceinline__ void cp4(uint32_t dst, const void* src, uint32_t ssz) {
    asm volatile("cp.async.ca.shared.global [%0], [%1], 4, %2;" :: "r"(dst), "l"(src), "r"(ssz));
}
__device__ __forceinline__ void cp_commit()   { asm volatile("cp.async.commit_group;" ::: "memory"); }
template<int N>
__device__ __forceinline__ void cp_wait_group() {
    asm volatile("cp.async.wait_group %0;" :: "n"(N) : "memory");
}

// ============================================================================
// SMEM layouts per 32-K chunk (4096 floats each = 16 KB):
//  A word((m,k)) = ((mt*4+ks)*4 + rgA)*32 + (m&7)*4 + (k&3)
//  B word((n,k)) = ((nt*4+ks)*2 + rg)*32 + (fl ^ swz(nt)),  fl=(k&3)*8+(n&7)
//      GEMM swz = (nt&3)*8 ;  CONV swz = (nt&3) | ((nt&4)<<2)
// Triple buffer: buffer i at byte offset i*32768; B at +16384 within buffer.
// ============================================================================

template<int CONV>
__device__ __forceinline__ void mma_chunk(const float* sA, const float* sB,
                                          int warpm, int warpn, int lane,
                                          float acc[2][8][4]) {
    const int fl0 = (lane & 3) * 8 + (lane >> 2);
    #pragma unroll
    for (int ks = 0; ks < 4; ks++) {
        uint32_t a[2][4];
        #pragma unroll
        for (int mt2 = 0; mt2 < 2; mt2++) {
            const float* pa = sA + ((warpm * 2 + mt2) * 4 + ks) * 128 + lane;
            a[mt2][0] = __float_as_uint(pa[0]);
            a[mt2][1] = __float_as_uint(pa[32]);
            a[mt2][2] = __float_as_uint(pa[64]);
            a[mt2][3] = __float_as_uint(pa[96]);
        }
        // software-pipelined B fragments (one nt ahead of the MMAs)
        auto ldb = [&](int nt2, uint32_t& b0, uint32_t& b1) {
            int nt  = warpn * 8 + nt2;
            int swz = CONV ? ((nt & 3) | ((nt & 4) << 2)) : ((nt & 3) * 8);
            int fx  = fl0 ^ swz;
            const float* pb = sB + (nt * 4 + ks) * 64;
            b0 = __float_as_uint(pb[fx]);
            b1 = __float_as_uint(pb[32 + fx]);
        };
        uint32_t b0c, b1c, b0n, b1n;
        ldb(0, b0c, b1c);
        #pragma unroll
        for (int nt2 = 0; nt2 < 8; nt2++) {
            if (nt2 < 7) ldb(nt2 + 1, b0n, b1n);
            mma_tf32(acc[0][nt2], a[0][0], a[0][1], a[0][2], a[0][3], b0c, b1c);
            mma_tf32(acc[1][nt2], a[1][0], a[1][1], a[1][2], a[1][3], b0c, b1c);
            b0c = b0n; b1c = b1n;
        }
    }
}

// ============================================================================
// Kernel 1: global average pool + tf32-round x into g_xr. grid=B*C, 256 thr.
// ============================================================================
__global__ void pool_round_kernel(const float* __restrict__ x) {
    int bc = blockIdx.x;
    const float4* p = (const float4*)(x + (size_t)bc * HW);
    float4* q = (float4*)(g_xr + (size_t)bc * HW);
    float s = 0.f;
    #pragma unroll
    for (int i = threadIdx.x; i < HW / 4; i += 256) {
        float4 v = p[i];
        s += (v.x + v.y) + (v.z + v.w);
        float4 r;
        r.x = to_tf32(v.x); r.y = to_tf32(v.y); r.z = to_tf32(v.z); r.w = to_tf32(v.w);
        q[i] = r;
    }
    __shared__ float red[8];
    #pragma unroll
    for (int o = 16; o > 0; o >>= 1) s += __shfl_down_sync(0xffffffffu, s, o);
    if ((threadIdx.x & 31) == 0) red[threadIdx.x >> 5] = s;
    __syncthreads();
    if (threadIdx.x < 8) {
        s = red[threadIdx.x];
        #pragma unroll
        for (int o = 4; o > 0; o >>= 1) s += __shfl_down_sync(0xffu, s, o);
        if (threadIdx.x == 0) g_pooled[bc] = s * (1.0f / (float)HW);
    }
}

// fused tf32 rounding of all three weight tensors (float4 granularity)
#define W1_F4 (EE * HID * CC / 4)
#define W2_F4 (EE * HID * HID * 9 / 4)
#define W3_F4 (EE * CC * HID / 4)
__global__ void round_all_kernel(const float* __restrict__ W1, const float* __restrict__ W2,
                                 const float* __restrict__ W3) {
    int i = blockIdx.x * 256 + threadIdx.x;
    const float4* src; float4* dst; int j;
    if (i < W1_F4)                 { src = (const float4*)W1; dst = (float4*)g_w1r; j = i; }
    else if (i < W1_F4 + W2_F4)    { src = (const float4*)W2; dst = (float4*)g_w2r; j = i - W1_F4; }
    else                           { src = (const float4*)W3; dst = (float4*)g_w3r; j = i - W1_F4 - W2_F4; }
    float4 v = src[j];
    float4 r;
    r.x = to_tf32(v.x); r.y = to_tf32(v.y); r.z = to_tf32(v.z); r.w = to_tf32(v.w);
    dst[j] = r;
}

// ============================================================================
// Kernel 2: router MLP + softmax + top-1.  grid = B, 128 threads.
// ============================================================================
__global__ void router_kernel(const float* __restrict__ Wr1, const float* __restrict__ br1,
                              const float* __restrict__ Wr2, const float* __restrict__ br2) {
    int b = blockIdx.x;
    int t = threadIdx.x;
    __shared__ float sp[CC];
    __shared__ float sh[RHD];
    __shared__ float slog[EE];
    sp[t]       = g_pooled[b * CC + t];
    sp[t + 128] = g_pooled[b * CC + t + 128];
    __syncthreads();
    {
        float acc = br1[t];
        const float* w = Wr1 + (size_t)t * CC;
        #pragma unroll 8
        for (int c = 0; c < CC; c++) acc = fmaf(sp[c], w[c], acc);
        sh[t] = fmaxf(acc, 0.f);
    }
    __syncthreads();
    if (t < EE) {
        float l = br2[t];
        const float* w = Wr2 + (size_t)t * RHD;
        #pragma unroll 8
        for (int r = 0; r < RHD; r++) l = fmaf(sh[r], w[r], l);
        slog[t] = l;
    }
    __syncthreads();
    if (t == 0) {
        float l0 = slog[0], l1 = slog[1], l2 = slog[2], l3 = slog[3];
        float m = fmaxf(fmaxf(l0, l1), fmaxf(l2, l3));
        float e0 = __expf(l0 - m), e1 = __expf(l1 - m), e2 = __expf(l2 - m), e3 = __expf(l3 - m);
        float s = e0 + e1 + e2 + e3;
        float p[4] = {e0 / s, e1 / s, e2 / s, e3 / s};
        int idx = 0; float v = p[0];
        #pragma unroll
        for (int i = 1; i < 4; i++) { if (p[i] > v) { v = p[i]; idx = i; } }
        g_expert[b] = idx;
        g_weight[b] = v / (v + 1e-9f);
    }
}

// ============================================================================
// Kernel 3: 1x1 conv C->HID + ReLU. GEMM M=128 N=4096 K=256 (8 chunks).
// 3-stage cp.async pipeline. grid=(32, B), 256 thr, 96KB dyn smem.
// ============================================================================
__global__ __launch_bounds__(256, 2) void gemm1_mma_kernel() {
    extern __shared__ float dsm[];
    const int tid = threadIdx.x, wid = tid >> 5, lane = tid & 31;
    const int warpm = wid >> 1, warpn = wid & 1;
    const int gid = lane >> 2, tig = lane & 3;
    int b  = blockIdx.y;
    int pt = blockIdx.x * 128;
    int e  = g_expert[b];
    const float* A  = g_w1r + (size_t)e * HID * CC;
    const float* Bx = g_xr  + (size_t)b * CC * HW + pt;

    int low = tid & 7, kq = (tid >> 3) & 7, mh0 = tid >> 6;
    int ak0 = kq * 4, amb = mh0 * 8 + low;
    uint32_t wA0 = (((mh0 >> 1) * 4 + (kq >> 1)) * 4 + ((mh0 & 1) | ((kq & 1) << 1))) * 32 + 4 * low;
    int nt_w = lane >> 1;
    uint32_t wBp[4];
    #pragma unroll
    for (int p = 0; p < 4; p++) {
        int kl = p * 8 + wid;
        wBp[p] = ((nt_w * 4 + (kl >> 3)) * 2 + ((kl >> 2) & 1)) * 32
               + (((kl & 3) ^ (nt_w & 3)) * 8) + (lane & 1) * 4;
    }
    uint32_t sm0 = cvta_s(dsm);

    float acc[2][8][4];
    #pragma unroll
    for (int i = 0; i < 2; i++)
        #pragma unroll
        for (int j = 0; j < 8; j++)
            #pragma unroll
            for (int r = 0; r < 4; r++) acc[i][j][r] = 0.f;

    auto load_chunk = [&](int kb, uint32_t base) {
        #pragma unroll
        for (int p = 0; p < 4; p++)
            cp16(base + (wA0 + 1024 * p) * 4, A + (size_t)(amb + 32 * p) * CC + kb + ak0);
        #pragma unroll
        for (int p = 0; p < 4; p++)
            cp16(base + 16384 + wBp[p] * 4, Bx + (size_t)(kb + p * 8 + wid) * HW + lane * 4);
    };

    load_chunk(0, sm0);       cp_commit();
    load_chunk(32, sm0 + 32768); cp_commit();

    int cur = 0, pf = 2;
    for (int it = 0; it < 8; it++) {
        cp_wait_group<1>();
        __syncthreads();
        if (it + 2 < 8) load_chunk((it + 2) * 32, sm0 + pf * 32768);
        cp_commit();     // empty group at the tail keeps wait_group semantics
        const float* sA = dsm + cur * 8192;
        mma_chunk<0>(sA, sA + 4096, warpm, warpn, lane, acc);
        cur = (cur == 2) ? 0 : cur + 1;
        pf  = (pf  == 2) ? 0 : pf  + 1;
    }

    float* Y = g_y1 + (size_t)b * HID * HW;
    #pragma unroll
    for (int mt2 = 0; mt2 < 2; mt2++) {
        int oc0 = warpm * 32 + mt2 * 16 + gid;
        #pragma unroll
        for (int nt2 = 0; nt2 < 8; nt2++) {
            int px = pt + warpn * 64 + nt2 * 8 + 2 * tig;
            float2 v0, v1;
            v0.x = to_tf32(fmaxf(acc[mt2][nt2][0], 0.f));
            v0.y = to_tf32(fmaxf(acc[mt2][nt2][1], 0.f));
            v1.x = to_tf32(fmaxf(acc[mt2][nt2][2], 0.f));
            v1.y = to_tf32(fmaxf(acc[mt2][nt2][3], 0.f));
            *(float2*)(Y + (size_t)oc0 * HW + px)       = v0;
            *(float2*)(Y + (size_t)(oc0 + 8) * HW + px) = v1;
        }
    }
}

// ============================================================================
// Kernel 4: 3x3 conv HID->HID + ReLU, implicit GEMM, K=1152 (36 chunks).
// 3-stage cp.async pipeline. grid=(32, B), 256 thr, 96KB dyn smem.
// ============================================================================
__global__ __launch_bounds__(256, 2) void conv3_mma_kernel() {
    extern __shared__ float dsm[];
    const int tid = threadIdx.x, wid = tid >> 5, lane = tid & 31;
    const int warpm = wid >> 1, warpn = wid & 1;
    const int gid = lane >> 2, tig = lane & 3;
    int b  = blockIdx.y;
    int pb = blockIdx.x;
    int pbase = pb << 7;
    int y0 = pb << 1;
    int e  = g_expert[b];
    const float* A  = g_w2r + (size_t)e * (HID * HID * 9);  // [128][1152]
    const float* Y1 = g_y1 + (size_t)b * HID * HW;

    int low = tid & 7, kq = (tid >> 3) & 7, mh0 = tid >> 6;
    int ak0 = kq * 4, amb = mh0 * 8 + low;
    uint32_t wA0 = (((mh0 >> 1) * 4 + (kq >> 1)) * 4 + ((mh0 & 1) | ((kq & 1) << 1))) * 32 + 4 * low;
    int nqL = lane & 15, kbit = lane >> 4;
    int klp[4], col0p[4], rowp[4], s01p[4];
    uint32_t wB0p[4];
    #pragma unroll
    for (int p = 0; p < 4; p++) {
        int kl = 2 * wid + kbit + 16 * (p & 1);
        int nq = nqL + 16 * (p >> 1);
        int n0 = nq * 4;
        int nt = nq >> 1;
        klp[p]   = kl;
        col0p[p] = n0 & 63;
        rowp[p]  = n0 >> 6;
        s01p[p]  = nt & 3;
        int fl0p = (kl & 3) * 8 + (nq & 1) * 4;
        wB0p[p]  = ((nt * 4 + (kl >> 3)) * 2 + ((kl >> 2) & 1)) * 32
                 + (fl0p ^ ((nt & 4) << 2));
    }
    uint32_t sm0 = cvta_s(dsm);

    float acc[2][8][4];
    #pragma unroll
    for (int i = 0; i < 2; i++)
        #pragma unroll
        for (int j = 0; j < 8; j++)
            #pragma unroll
            for (int r = 0; r < 4; r++) acc[i][j][r] = 0.f;

    auto load_chunk = [&](int kb, uint32_t base) {
        #pragma unroll
        for (int p = 0; p < 4; p++)
            cp16(base + (wA0 + 1024 * p) * 4, A + (size_t)(amb + 32 * p) * 1152 + kb + ak0);
        uint32_t bB = base + 16384;
        #pragma unroll
        for (int p = 0; p < 4; p++) {
            int k   = kb + klp[p];
            int ic  = k / 9;
            int tap = k - ic * 9;
            int ky  = tap / 3;
            int dx  = tap - ky * 3 - 1;
            int gy  = y0 + rowp[p] + ky - 1;
            bool vy = ((unsigned)gy < 64u);
            const float* srow = Y1 + (size_t)ic * HW + (gy << 6);
            #pragma unroll
            for (int j = 0; j < 4; j++) {
                int gx  = col0p[p] + j + dx;
                bool ok = vy & ((unsigned)gx < 64u);
                cp4(bB + (wB0p[p] + (j ^ s01p[p])) * 4, ok ? (srow + gx) : Y1, ok ? 4u : 0u);
            }
        }
    };

    load_chunk(0, sm0);          cp_commit();
    load_chunk(32, sm0 + 32768); cp_commit();

    int cur = 0, pf = 2;
    for (int it = 0; it < 36; it++) {
        cp_wait_group<1>();
        __syncthreads();
        if (it + 2 < 36) load_chunk((it + 2) * 32, sm0 + pf * 32768);
        cp_commit();
        const float* sA = dsm + cur * 8192;
        mma_chunk<1>(sA, sA + 4096, warpm, warpn, lane, acc);
        cur = (cur == 2) ? 0 : cur + 1;
        pf  = (pf  == 2) ? 0 : pf  + 1;
    }

    float* Y2 = g_y2 + (size_t)b * HID * HW;
    #pragma unroll
    for (int mt2 = 0; mt2 < 2; mt2++) {
        int oc0 = warpm * 32 + mt2 * 16 + gid;
        #pragma unroll
        for (int nt2 = 0; nt2 < 8; nt2++) {
            int px = pbase + warpn * 64 + nt2 * 8 + 2 * tig;
            float2 v0, v1;
            v0.x = to_tf32(fmaxf(acc[mt2][nt2][0], 0.f));
            v0.y = to_tf32(fmaxf(acc[mt2][nt2][1], 0.f));
            v1.x = to_tf32(fmaxf(acc[mt2][nt2][2], 0.f));
            v1.y = to_tf32(fmaxf(acc[mt2][nt2][3], 0.f));
            *(float2*)(Y2 + (size_t)oc0 * HW + px)       = v0;
            *(float2*)(Y2 + (size_t)(oc0 + 8) * HW + px) = v1;
        }
    }
}

// ============================================================================
// Kernel 5: 1x1 conv HID->C * wgt + residual. GEMM M=256 N=4096 K=128.
// 3-stage cp.async pipeline. grid=(32, 2, B), 256 thr, 96KB dyn smem.
// ============================================================================
__global__ __launch_bounds__(256, 2) void gemm3_mma_kernel(const float* __restrict__ x,
                                                           float* __restrict__ out) {
    extern __shared__ float dsm[];
    const int tid = threadIdx.x, wid = tid >> 5, lane = tid & 31;
    const int warpm = wid >> 1, warpn = wid & 1;
    const int gid = lane >> 2, tig = lane & 3;
    int b  = blockIdx.z;
    int m0 = blockIdx.y * 128;
    int pt = blockIdx.x * 128;
    int e  = g_expert[b];
    float wgt = g_weight[b];
    const float* A  = g_w3r + (size_t)e * (CC * HID) + (size_t)m0 * HID;
    const float* Bx = g_y2  + (size_t)b * HID * HW + pt;

    int low = tid & 7, kq = (tid >> 3) & 7, mh0 = tid >> 6;
    int ak0 = kq * 4, amb = mh0 * 8 + low;
    uint32_t wA0 = (((mh0 >> 1) * 4 + (kq >> 1)) * 4 + ((mh0 & 1) | ((kq & 1) << 1))) * 32 + 4 * low;
    int nt_w = lane >> 1;
    uint32_t wBp[4];
    #pragma unroll
    for (int p = 0; p < 4; p++) {
        int kl = p * 8 + wid;
        wBp[p] = ((nt_w * 4 + (kl >> 3)) * 2 + ((kl >> 2) & 1)) * 32
               + (((kl & 3) ^ (nt_w & 3)) * 8) + (lane & 1) * 4;
    }
    uint32_t sm0 = cvta_s(dsm);

    float acc[2][8][4];
    #pragma unroll
    for (int i = 0; i < 2; i++)
        #pragma unroll
        for (int j = 0; j < 8; j++)
            #pragma unroll
            for (int r = 0; r < 4; r++) acc[i][j][r] = 0.f;

    auto load_chunk = [&](int kb, uint32_t base) {
        #pragma unroll
        for (int p = 0; p < 4; p++)
            cp16(base + (wA0 + 1024 * p) * 4, A + (size_t)(amb + 32 * p) * HID + kb + ak0);
        #pragma unroll
        for (int p = 0; p < 4; p++)
            cp16(base + 16384 + wBp[p] * 4, Bx + (size_t)(kb + p * 8 + wid) * HW + lane * 4);
    };

    load_chunk(0, sm0);          cp_commit();
    load_chunk(32, sm0 + 32768); cp_commit();

    int cur = 0, pf = 2;
    for (int it = 0; it < 4; it++) {
        cp_wait_group<1>();
        __syncthreads();
        if (it + 2 < 4) load_chunk((it + 2) * 32, sm0 + pf * 32768);
        cp_commit();
        const float* sA = dsm + cur * 8192;
        mma_chunk<0>(sA, sA + 4096, warpm, warpn, lane, acc);
        cur = (cur == 2) ? 0 : cur + 1;
        pf  = (pf  == 2) ? 0 : pf  + 1;
    }

    const float* Xb = x   + (size_t)b * CC * HW;
    float*       O  = out + (size_t)b * CC * HW;
    #pragma unroll
    for (int mt2 = 0; mt2 < 2; mt2++) {
        int m_lo = m0 + warpm * 32 + mt2 * 16 + gid;
        int m_hi = m_lo + 8;
        #pragma unroll
        for (int nt2 = 0; nt2 < 8; nt2++) {
            int px = pt + warpn * 64 + nt2 * 8 + 2 * tig;
            float2 x0 = *(const float2*)(Xb + (size_t)m_lo * HW + px);
            float2 x1 = *(const float2*)(Xb + (size_t)m_hi * HW + px);
            float2 v0, v1;
            v0.x = fmaf(wgt, acc[mt2][nt2][0], x0.x);
            v0.y = fmaf(wgt, acc[mt2][nt2][1], x0.y);
            v1.x = fmaf(wgt, acc[mt2][nt2][2], x1.x);
            v1.y = fmaf(wgt, acc[mt2][nt2][3], x1.y);
            *(float2*)(O + (size_t)m_lo * HW + px) = v0;
            *(float2*)(O + (size_t)m_hi * HW + px) = v1;
        }
    }
}

// ============================================================================
extern "C" void kernel_launch(void* const* d_in, const int* in_sizes, int n_in,
                              void* d_out, int out_size) {
    const float* x   = (const float*)d_in[0];
    const float* Wr1 = (const float*)d_in[1];
    const float* br1 = (const float*)d_in[2];
    const float* Wr2 = (const float*)d_in[3];
    const float* br2 = (const float*)d_in[4];
    const float* W1  = (const float*)d_in[5];
    const float* W2  = (const float*)d_in[6];
    const float* W3  = (const float*)d_in[7];
    float* out = (float*)d_out;

    cudaFuncSetAttribute(gemm1_mma_kernel, cudaFuncAttributeMaxDynamicSharedMemorySize, 98304);
    cudaFuncSetAttribute(conv3_mma_kernel, cudaFuncAttributeMaxDynamicSharedMemorySize, 98304);
    cudaFuncSetAttribute(gemm3_mma_kernel, cudaFuncAttributeMaxDynamicSharedMemorySize, 98304);

    pool_round_kernel<<<BB * CC, 256>>>(x);
    round_all_kernel <<<(W1_F4 + W2_F4 + W3_F4 + 255) / 256, 256>>>(W1, W2, W3);
    router_kernel    <<<BB, 128>>>(Wr1, br1, Wr2, br2);
    gemm1_mma_kernel <<<dim3(32, BB), 256, 98304>>>();
    conv3_mma_kernel <<<dim3(32, BB), 256, 98304>>>();
    gemm3_mma_kernel <<<dim3(32, 2, BB), 256, 98304>>>(x, out);
}